// round 3
// baseline (speedup 1.0000x reference)
#include <cuda_runtime.h>
#include <cuda_bf16.h>

// Problem constants
#define BB   8
#define CC   28
#define HH   256
#define WW   256
#define DG   7
#define CPG  4
#define KH   7
#define NGI  49
#define PADH 3

// smem region sizes (floats)
#define NS_WS1P (NGI*CC*CPG)     // 5488 : stage1 weights [gi][o][c]
#define NS_W2P  (CC*14*8*2)      // 6272 : stage2 weights [o][ip][j(8)][par]
#define MIDW    264              // 3 zero + 256 + 5 zero
#define NS_MID2 (14*MIDW*2)      // 7392 : mid, i-pair interleaved [ip][col][par]
#define NS_SAMP (2*2*WW*2)       // 2048 : double-buffered [buf][cp][w][par]

// ---------------------------------------------------------------------------
__device__ int   d_y0[NGI*HH];
__device__ int   d_y1[NGI*HH];
__device__ float d_wt0[NGI*HH];
__device__ float d_wt1[NGI*HH];
__device__ float d_ws1p[NS_WS1P];
__device__ float d_w2p[NS_W2P];
__device__ float d_B2[CC];

// packed f32x2 FMA: d = a*b + d  (lo/hi lanes independent)
__device__ __forceinline__ void ffma2(unsigned long long& d,
                                      unsigned long long a,
                                      unsigned long long b) {
    asm("fma.rn.f32x2 %0, %1, %2, %0;" : "+l"(d) : "l"(a), "l"(b));
}
__device__ __forceinline__ float lo32(unsigned long long v) {
    return __int_as_float((int)(unsigned int)v);
}
__device__ __forceinline__ float hi32(unsigned long long v) {
    return __int_as_float((int)(v >> 32));
}
// bank-conflict swizzle: toggle bit2 (16B unit) by bit5 of the float offset
__device__ __forceinline__ int swz(int fi) {
    return fi ^ (((fi >> 5) & 1) << 2);
}

// ---------------------------------------------------------------------------
// Setup 1: harmonic sampling tables (yp collapses to (h+1)(i+1)/(g+1)-4).
// ---------------------------------------------------------------------------
__global__ void setup_tables_kernel() {
    int idx = blockIdx.x * blockDim.x + threadIdx.x;
    if (idx >= NGI * HH) return;
    int gi = idx / HH;
    int h  = idx % HH;
    int g  = gi / KH;
    int i  = gi % KH;

    float fh = (float)h, fg = (float)g, fi = (float)i;
    float t   = __fdiv_rn(fh + 1.0f, fg + 1.0f) * (fi + 1.0f);
    float off = -fi + t - (fh + 1.0f);
    float yp  = fh - (float)PADH + fi + off;

    float y0f = floorf(yp);
    float fy  = yp - y0f;
    int   y0i = (int)y0f;

    float v0 = (y0i >= 0 && y0i <= HH - 1) ? 1.0f : 0.0f;
    float v1 = (y0i + 1 >= 0 && y0i + 1 <= HH - 1) ? 1.0f : 0.0f;

    int y0c = y0i < 0 ? 0 : (y0i > HH - 1 ? HH - 1 : y0i);
    int y1i = y0i + 1;
    int y1c = y1i < 0 ? 0 : (y1i > HH - 1 ? HH - 1 : y1i);

    d_y0[idx]  = y0c;
    d_y1[idx]  = y1c;
    d_wt0[idx] = (1.0f - fy) * v0;
    d_wt1[idx] = fy * v1;
}

// ---------------------------------------------------------------------------
// Setup 2: packed weight layouts + conv/group-mix fusion.
//   ws1p[gi][o][c]          = weight[o, g*4+c, i]
//   w2p[o][ip][j][par]      = sum_g w_m[f,g] * w_t[4g+cc, 2ip+par, 0, j]
//   B2[o]                   = sum_g w_m[f,g] * b_t[4g+cc] + b_m[f]
// ---------------------------------------------------------------------------
__global__ void setup_weights_kernel(const float* __restrict__ weight,
                                     const float* __restrict__ w_t,
                                     const float* __restrict__ b_t,
                                     const float* __restrict__ w_m,
                                     const float* __restrict__ b_m) {
    int idx = blockIdx.x * blockDim.x + threadIdx.x;
    if (idx < NS_WS1P) {
        int gi = idx / (CC * CPG);
        int r  = idx % (CC * CPG);
        int o  = r / CPG;
        int c  = r % CPG;
        int g  = gi / KH;
        int i  = gi % KH;
        d_ws1p[idx] = weight[(o * CC + g * CPG + c) * KH + i];
    }
    if (idx < NS_W2P) {
        int o   = idx / 224;          // 14*8*2
        int r   = idx % 224;
        int ip  = r / 16;
        int r2  = r % 16;
        int j   = r2 >> 1;
        int par = r2 & 1;
        float v = 0.0f;
        if (j < 7) {
            int i2 = ip * 2 + par;
            int f  = o / CPG;
            int cc = o % CPG;
            #pragma unroll
            for (int g = 0; g < DG; g++)
                v += w_m[f * DG + g] * w_t[((g * CPG + cc) * CC + i2) * KH + j];
        }
        d_w2p[idx] = v;
    }
    if (idx < CC) {
        int f  = idx / CPG;
        int cc = idx % CPG;
        float s = b_m[idx / CPG];
        #pragma unroll
        for (int g = 0; g < DG; g++)
            s += w_m[f * DG + g] * b_t[g * CPG + cc];
        d_B2[idx] = s;
    }
}

// ---------------------------------------------------------------------------
// Fused main kernel, FFMA2 (f32x2) packed over the reduction-dim parity.
// One block per (b,h) output row; thread = (to: 7 outputs, tw: 4 pixels).
// ---------------------------------------------------------------------------
__global__ void __launch_bounds__(256, 2)
harmonic_fused_kernel(const float* __restrict__ x,
                      const float* __restrict__ bias,
                      float* __restrict__ out) {
    extern __shared__ float sm[];
    float* s_ws1p = sm;                      // 5488
    float* s_w2p  = s_ws1p + NS_WS1P;        // 6272
    float* s_mid2 = s_w2p  + NS_W2P;         // 7392
    float* s_samp = s_mid2 + NS_MID2;        // 2048
    float* s_w0   = s_samp + NS_SAMP;        // 49
    float* s_w1   = s_w0 + NGI;              // 49
    float* s_B2   = s_w1 + NGI;              // 28
    float* s_bias = s_B2 + CC;               // 28
    int*   s_y0   = (int*)(s_bias + CC);     // 49
    int*   s_y1   = s_y0 + NGI;              // 49

    const int tid = threadIdx.x;
    const int h   = blockIdx.x & (HH - 1);
    const int b   = blockIdx.x >> 8;
    const int tw  = tid & 63;
    const int to  = tid >> 6;
    const int w0  = tw << 2;

    // ---- prologue: stage weights & tables ----
    for (int idx = tid; idx < NS_WS1P; idx += 256) s_ws1p[idx] = d_ws1p[idx];
    for (int idx = tid; idx < NS_W2P;  idx += 256) s_w2p[idx]  = d_w2p[idx];
    if (tid < NGI) {
        int t = tid * HH + h;
        s_w0[tid] = d_wt0[t];
        s_w1[tid] = d_wt1[t];
        s_y0[tid] = d_y0[t];
        s_y1[tid] = d_y1[t];
    }
    if (tid < CC) {
        s_B2[tid]   = d_B2[tid];
        s_bias[tid] = bias[tid];
    }
    // zero halo (cols 0..2 and 259..263, both parities, all 14 ip rows)
    if (tid < 224) {
        int ip = tid >> 4, r = tid & 15, par = r & 1, ci = r >> 1;
        int col = ci < 3 ? ci : 256 + ci;
        s_mid2[swz(ip * (MIDW * 2) + col * 2 + par)] = 0.0f;
    }

    const float* xb = x + (size_t)b * CC * HH * WW;

    // precomputed swizzled addresses (buffer 0)
    const int pst0 = swz(tid * 2);            // producer cp0
    const int pst1 = swz(512 + tid * 2);      // producer cp1
    const int cl00 = swz(w0 * 2);             // consumer cp0 pixels 0,1
    const int cl01 = swz(w0 * 2 + 4);         // consumer cp0 pixels 2,3
    const int cl10 = swz(512 + w0 * 2);       // consumer cp1 pixels 0,1
    const int cl11 = swz(512 + w0 * 2 + 4);   // consumer cp1 pixels 2,3

    // ---- pre-sample tap 0 into buffer 0 ----
    {
        int t0 = h;                 // gi=0
        int r0 = d_y0[t0], r1 = d_y1[t0];
        float f0 = d_wt0[t0], f1 = d_wt1[t0];
        float a[4];
        #pragma unroll
        for (int c = 0; c < CPG; c++) {
            float v0 = __ldg(xb + (c * HH + r0) * WW + tid);
            float v1 = __ldg(xb + (c * HH + r1) * WW + tid);
            a[c] = v0 * f0 + v1 * f1;
        }
        *(float2*)(s_samp + pst0) = make_float2(a[0], a[1]);
        *(float2*)(s_samp + pst1) = make_float2(a[2], a[3]);
    }
    __syncthreads();

    unsigned long long acc[7][4];
    #pragma unroll
    for (int k = 0; k < 7; k++)
        #pragma unroll
        for (int m = 0; m < 4; m++) acc[k][m] = 0ULL;

    // ---- stage 1: 49 taps, double-buffered, FFMA2 over (c-even,c-odd) ----
    #pragma unroll 1
    for (int gi = 0; gi < NGI; gi++) {
        const int cur = gi & 1;
        if (gi < NGI - 1) {
            int gn = gi + 1;
            int g  = gn / KH;
            int r0 = s_y0[gn], r1 = s_y1[gn];
            float f0 = s_w0[gn], f1 = s_w1[gn];
            const float* pc = xb + (g * CPG) * (HH * WW);
            float* db = s_samp + (cur ^ 1) * 1024;
            float a[4];
            #pragma unroll
            for (int c = 0; c < CPG; c++) {
                float v0 = __ldg(pc + (c * HH + r0) * WW + tid);
                float v1 = __ldg(pc + (c * HH + r1) * WW + tid);
                a[c] = v0 * f0 + v1 * f1;
            }
            *(float2*)(db + pst0) = make_float2(a[0], a[1]);
            *(float2*)(db + pst1) = make_float2(a[2], a[3]);
        }

        const float* sb = s_samp + cur * 1024;
        ulonglong2 d00 = *(const ulonglong2*)(sb + cl00);
        ulonglong2 d01 = *(const ulonglong2*)(sb + cl01);
        ulonglong2 d10 = *(const ulonglong2*)(sb + cl10);
        ulonglong2 d11 = *(const ulonglong2*)(sb + cl11);

        const float* wb = s_ws1p + (gi * CC + to * 7) * CPG;
        #pragma unroll
        for (int k = 0; k < 7; k++) {
            ulonglong2 wq = *(const ulonglong2*)(wb + k * 4);  // (c0,c1),(c2,c3)
            ffma2(acc[k][0], d00.x, wq.x);
            ffma2(acc[k][1], d00.y, wq.x);
            ffma2(acc[k][2], d01.x, wq.x);
            ffma2(acc[k][3], d01.y, wq.x);
            ffma2(acc[k][0], d10.x, wq.y);
            ffma2(acc[k][1], d10.y, wq.y);
            ffma2(acc[k][2], d11.x, wq.y);
            ffma2(acc[k][3], d11.y, wq.y);
        }
        __syncthreads();
    }

    // ---- write mid (+bias) into i-pair interleaved layout ----
    #pragma unroll
    for (int k = 0; k < 7; k++) {
        int o  = to * 7 + k;
        int ip = o >> 1;
        int par = o & 1;
        float bs = s_bias[o];
        #pragma unroll
        for (int m = 0; m < 4; m++) {
            float v = lo32(acc[k][m]) + hi32(acc[k][m]) + bs;
            s_mid2[swz(ip * (MIDW * 2) + (3 + w0 + m) * 2 + par)] = v;
        }
    }
    __syncthreads();

    // ---- stage 2: fused 1x7 conv + group mix, FFMA2 over (i-even,i-odd) ----
    unsigned long long acc2[7][4];
    #pragma unroll
    for (int k = 0; k < 7; k++)
        #pragma unroll
        for (int m = 0; m < 4; m++) acc2[k][m] = 0ULL;

    const float* w2b = s_w2p + (to * 7) * 224;
    #pragma unroll 1
    for (int ip = 0; ip < 14; ip++) {
        int base = ip * (MIDW * 2) + w0 * 2;    // window cols w0..w0+9 (padded)
        ulonglong2 q0 = *(const ulonglong2*)(s_mid2 + swz(base));
        ulonglong2 q1 = *(const ulonglong2*)(s_mid2 + swz(base + 4));
        ulonglong2 q2 = *(const ulonglong2*)(s_mid2 + swz(base + 8));
        ulonglong2 q3 = *(const ulonglong2*)(s_mid2 + swz(base + 12));
        ulonglong2 q4 = *(const ulonglong2*)(s_mid2 + swz(base + 16));
        unsigned long long m2[10] = {q0.x, q0.y, q1.x, q1.y, q2.x,
                                     q2.y, q3.x, q3.y, q4.x, q4.y};
        #pragma unroll
        for (int k = 0; k < 7; k++) {
            const float* wkb = w2b + k * 224 + ip * 16;
            ulonglong2 wa = *(const ulonglong2*)(wkb);
            ulonglong2 wbq = *(const ulonglong2*)(wkb + 4);
            ulonglong2 wc = *(const ulonglong2*)(wkb + 8);
            ulonglong2 wd = *(const ulonglong2*)(wkb + 12);
            unsigned long long wj[7] = {wa.x, wa.y, wbq.x, wbq.y,
                                        wc.x, wc.y, wd.x};
            #pragma unroll
            for (int j = 0; j < 7; j++)
                #pragma unroll
                for (int m = 0; m < 4; m++)
                    ffma2(acc2[k][m], m2[j + m], wj[j]);
        }
    }

    // ---- store output row ----
    #pragma unroll
    for (int k = 0; k < 7; k++) {
        int o = to * 7 + k;
        float bq = s_B2[o];
        float4 v;
        v.x = lo32(acc2[k][0]) + hi32(acc2[k][0]) + bq;
        v.y = lo32(acc2[k][1]) + hi32(acc2[k][1]) + bq;
        v.z = lo32(acc2[k][2]) + hi32(acc2[k][2]) + bq;
        v.w = lo32(acc2[k][3]) + hi32(acc2[k][3]) + bq;
        *(float4*)(out + ((size_t)(b * CC + o) * HH + h) * WW + w0) = v;
    }
}

// ---------------------------------------------------------------------------
extern "C" void kernel_launch(void* const* d_in, const int* in_sizes, int n_in,
                              void* d_out, int out_size) {
    const float* x      = (const float*)d_in[0];
    const float* weight = (const float*)d_in[1];
    const float* bias   = (const float*)d_in[2];
    const float* w_t    = (const float*)d_in[3];
    const float* b_t    = (const float*)d_in[4];
    const float* w_m    = (const float*)d_in[5];
    const float* b_m    = (const float*)d_in[6];
    float* out = (float*)d_out;

    setup_tables_kernel<<<(NGI * HH + 255) / 256, 256>>>();
    setup_weights_kernel<<<(NS_W2P + 255) / 256, 256>>>(weight, w_t, b_t, w_m, b_m);

    const int smem_bytes =
        (NS_WS1P + NS_W2P + NS_MID2 + NS_SAMP + NGI * 2 + CC * 2 + NGI * 2) * 4;
    cudaFuncSetAttribute(harmonic_fused_kernel,
                         cudaFuncAttributeMaxDynamicSharedMemorySize, smem_bytes);
    harmonic_fused_kernel<<<BB * HH, 256, smem_bytes>>>(x, bias, out);
}

// round 5
// speedup vs baseline: 1.1883x; 1.1883x over previous
#include <cuda_runtime.h>
#include <cstdint>

#define BBATCH 8
#define CCH    28
#define HHH    256
#define WWW    256
#define KHH    7
#define NGI    49
#define HW     (HHH*WWW)
#define PADH   3

// smem float-index layout
#define BF_HALF   7168              // per-part B-fragment floats (28 steps x 4 nt x 64)
#define BF_SIZE   (2*BF_HALF)       // 14336
#define MID_W     268               // 3 zero + 256 data + pad; %32=12 -> conflict-free epi
#define MID_OFF   BF_SIZE           // 14336
#define MID_SIZE  (CCH*MID_W)       // 7504
#define TBL_OFF   (MID_OFF+MID_SIZE) // 21840
// tables: f0[56] f1[56] y0[56] y1[56] pl[56] b1[28] B2[28]
#define SMEM_FLOATS (TBL_OFF + 56*5 + 28*2)
#define SMEM_BYTES  (SMEM_FLOATS*4)

static __device__ __forceinline__ void mma8(float* d,
                                            uint32_t a0, uint32_t a1,
                                            uint32_t a2, uint32_t a3,
                                            uint32_t b0, uint32_t b1) {
    asm volatile(
        "mma.sync.aligned.m16n8k8.row.col.f32.tf32.tf32.f32 "
        "{%0,%1,%2,%3}, {%4,%5,%6,%7}, {%8,%9}, {%0,%1,%2,%3};"
        : "+f"(d[0]), "+f"(d[1]), "+f"(d[2]), "+f"(d[3])
        : "r"(a0), "r"(a1), "r"(a2), "r"(a3), "r"(b0), "r"(b1));
}
static __device__ __forceinline__ void split(float v, uint32_t& h, uint32_t& l) {
    uint32_t hb = __float_as_uint(v) & 0xffffe000u;
    h = hb;
    l = __float_as_uint(v - __uint_as_float(hb));
}

__global__ void __launch_bounds__(256)
harmonic_mma_kernel(const float* __restrict__ x,
                    const float* __restrict__ weight,
                    const float* __restrict__ bias,
                    const float* __restrict__ w_t,
                    const float* __restrict__ b_t,
                    const float* __restrict__ w_m,
                    const float* __restrict__ b_m,
                    float* __restrict__ out) {
    extern __shared__ float sm[];
    float* s_bf  = sm;                    // [part][step][nt][lane*2+r]
    float* s_mid = sm + MID_OFF;          // [28][268]
    float* s_f0  = sm + TBL_OFF;
    float* s_f1  = s_f0 + 56;
    int*   s_y0  = (int*)(s_f1 + 56);
    int*   s_y1  = s_y0 + 56;
    int*   s_pl  = s_y1 + 56;
    float* s_b1  = (float*)(s_pl + 56);
    float* s_B2  = s_b1 + 28;

    const int tid  = threadIdx.x;
    const int wid  = tid >> 5;
    const int lane = tid & 31;
    const int g    = lane >> 2;
    const int tig  = lane & 3;
    const int h    = blockIdx.x & 255;
    const int b    = blockIdx.x >> 8;
    const int mbase = wid * 32;
    const int m0    = mbase + g;

    // ---- harmonic tables for this h ----
    if (tid < NGI) {
        int gg = tid / KHH, ii = tid % KHH;
        float fh = (float)h, fg = (float)gg, fi = (float)ii;
        float t   = __fdiv_rn(fh + 1.0f, fg + 1.0f) * (fi + 1.0f);
        float off = -fi + t - (fh + 1.0f);
        float yp  = fh - (float)PADH + fi + off;
        float y0f = floorf(yp);
        float fy  = yp - y0f;
        int   y0i = (int)y0f;
        float v0 = (y0i >= 0 && y0i <= HHH - 1) ? 1.0f : 0.0f;
        float v1 = (y0i + 1 >= 0 && y0i + 1 <= HHH - 1) ? 1.0f : 0.0f;
        int y0c = y0i < 0 ? 0 : (y0i > HHH - 1 ? HHH - 1 : y0i);
        int y1i = y0i + 1;
        int y1c = y1i < 0 ? 0 : (y1i > HHH - 1 ? HHH - 1 : y1i);
        s_y0[tid] = y0c * WWW;
        s_y1[tid] = y1c * WWW;
        s_f0[tid] = (1.0f - fy) * v0;
        s_f1[tid] = fy * v1;
        s_pl[tid] = (tid / KHH) * 4;
    }
    if (tid < CCH) {
        s_b1[tid] = bias[tid];
        int f = tid >> 2, cq = tid & 3;
        float s = b_m[f];
        #pragma unroll
        for (int g7 = 0; g7 < 7; ++g7) s += w_m[f * 7 + g7] * b_t[g7 * 4 + cq];
        s_B2[tid] = s;
    }

    // ---- B1 fragment fill: k = gi*4 + c ----
    for (int idx = tid; idx < BF_HALF; idx += 256) {
        int s  = idx >> 8;
        int w  = idx & 255;
        int nt = w >> 6;
        int l2 = w & 63;
        int ln = l2 >> 1, rr = l2 & 1;
        int gg = ln >> 2, tt = ln & 3;
        int n  = nt * 8 + gg;
        int k  = 8 * s + tt + 4 * rr;
        int gi = k >> 2, c = k & 3;
        float v = 0.0f;
        if (n < CCH && gi < NGI)
            v = weight[(n * CCH + (gi / KHH) * 4 + c) * KHH + (gi % KHH)];
        uint32_t hb, lb;
        split(v, hb, lb);
        s_bf[idx]           = __uint_as_float(hb);
        s_bf[BF_HALF + idx] = __uint_as_float(lb);
    }
    __syncthreads();

    const float* xb = x + (size_t)b * CCH * HW;

    // =================== STAGE 1 ===================
    float acc[2][4][4];
    #pragma unroll
    for (int t = 0; t < 2; ++t)
        #pragma unroll
        for (int nt = 0; nt < 4; ++nt)
            #pragma unroll
            for (int r = 0; r < 4; ++r) acc[t][nt][r] = 0.0f;

    #pragma unroll 2
    for (int s = 0; s < 28; ++s) {
        int gi0 = 2 * s, gi1 = 2 * s + 1;
        int c0 = gi0 > 48 ? 48 : gi0;
        int c1 = gi1 > 48 ? 48 : gi1;
        float f00 = s_f0[c0], f01 = s_f1[c0];
        float f10 = s_f0[c1], f11 = s_f1[c1];
        int o00 = s_y0[c0], o01 = s_y1[c0];
        int o10 = s_y0[c1], o11 = s_y1[c1];
        const float* p0 = xb + (size_t)(s_pl[c0] + tig) * HW;
        const float* p1 = xb + (size_t)(s_pl[c1] + tig) * HW;

        uint32_t ah[8], al[8];
        #pragma unroll
        for (int q = 0; q < 4; ++q) {
            int mq = m0 + 8 * q;
            float v0 = __ldg(p0 + o00 + mq) * f00 + __ldg(p0 + o01 + mq) * f01;
            float v1 = __ldg(p1 + o10 + mq) * f10 + __ldg(p1 + o11 + mq) * f11;
            split(v0, ah[q], al[q]);
            split(v1, ah[4 + q], al[4 + q]);
        }
        const float* bfs = s_bf + s * 256 + lane * 2;
        #pragma unroll
        for (int nt = 0; nt < 4; ++nt) {
            float2 bhf = *(const float2*)(bfs + nt * 64);
            float2 blf = *(const float2*)(bfs + BF_HALF + nt * 64);
            uint32_t bh0 = __float_as_uint(bhf.x), bh1 = __float_as_uint(bhf.y);
            uint32_t bl0 = __float_as_uint(blf.x), bl1 = __float_as_uint(blf.y);
            #pragma unroll
            for (int t = 0; t < 2; ++t) {
                float* D = acc[t][nt];
                mma8(D, ah[2*t], ah[2*t+1], ah[4+2*t], ah[4+2*t+1], bh0, bh1);
                mma8(D, al[2*t], al[2*t+1], al[4+2*t], al[4+2*t+1], bh0, bh1);
                mma8(D, ah[2*t], ah[2*t+1], ah[4+2*t], ah[4+2*t+1], bl0, bl1);
            }
        }
    }

    // ---- epilogue 1: acc -> mid (+bias), plus halo zeros ----
    #pragma unroll
    for (int t = 0; t < 2; ++t) {
        int r0 = mbase + 16 * t + g;
        #pragma unroll
        for (int nt = 0; nt < 4; ++nt) {
            int n0 = nt * 8 + tig * 2;
            int n1 = n0 + 1;
            if (n0 < CCH) {
                float bq = s_b1[n0];
                s_mid[n0 * MID_W + 3 + r0]     = acc[t][nt][0] + bq;
                s_mid[n0 * MID_W + 3 + r0 + 8] = acc[t][nt][2] + bq;
            }
            if (n1 < CCH) {
                float bq = s_b1[n1];
                s_mid[n1 * MID_W + 3 + r0]     = acc[t][nt][1] + bq;
                s_mid[n1 * MID_W + 3 + r0 + 8] = acc[t][nt][3] + bq;
            }
        }
    }
    if (tid < 196) {   // zero cols 0..2 and 259..262 for each of 28 rows
        int i = tid / 7, p = tid % 7;
        int col = (p < 3) ? p : 256 + p;
        s_mid[i * MID_W + col] = 0.0f;
    }
    __syncthreads();

    // ---- B2 fragment fill: k = i2*8 + j (j=7 pad), fused conv∘mix ----
    for (int idx = tid; idx < BF_HALF; idx += 256) {
        int s  = idx >> 8;
        int w  = idx & 255;
        int nt = w >> 6;
        int l2 = w & 63;
        int ln = l2 >> 1, rr = l2 & 1;
        int gg = ln >> 2, tt = ln & 3;
        int n  = nt * 8 + gg;
        int j  = tt + 4 * rr;
        float v = 0.0f;
        if (n < CCH && j < KHH) {
            int f = n >> 2, cq = n & 3;
            #pragma unroll
            for (int g7 = 0; g7 < 7; ++g7)
                v += w_m[f * 7 + g7] * w_t[((g7 * 4 + cq) * CCH + s) * KHH + j];
        }
        uint32_t hb, lb;
        split(v, hb, lb);
        s_bf[idx]           = __uint_as_float(hb);
        s_bf[BF_HALF + idx] = __uint_as_float(lb);
    }
    __syncthreads();

    // =================== STAGE 2 ===================
    float acc2[2][4][4];
    #pragma unroll
    for (int t = 0; t < 2; ++t)
        #pragma unroll
        for (int nt = 0; nt < 4; ++nt)
            #pragma unroll
            for (int r = 0; r < 4; ++r) acc2[t][nt][r] = 0.0f;

    #pragma unroll 2
    for (int s = 0; s < 28; ++s) {
        const float* mr = s_mid + s * MID_W + m0;
        uint32_t ah[8], al[8];
        #pragma unroll
        for (int q = 0; q < 4; ++q) {
            float v0 = mr[8 * q + tig];
            float v1 = mr[8 * q + tig + 4];
            split(v0, ah[q], al[q]);
            split(v1, ah[4 + q], al[4 + q]);
        }
        const float* bfs = s_bf + s * 256 + lane * 2;
        #pragma unroll
        for (int nt = 0; nt < 4; ++nt) {
            float2 bhf = *(const float2*)(bfs + nt * 64);
            float2 blf = *(const float2*)(bfs + BF_HALF + nt * 64);
            uint32_t bh0 = __float_as_uint(bhf.x), bh1 = __float_as_uint(bhf.y);
            uint32_t bl0 = __float_as_uint(blf.x), bl1 = __float_as_uint(blf.y);
            #pragma unroll
            for (int t = 0; t < 2; ++t) {
                float* D = acc2[t][nt];
                mma8(D, ah[2*t], ah[2*t+1], ah[4+2*t], ah[4+2*t+1], bh0, bh1);
                mma8(D, al[2*t], al[2*t+1], al[4+2*t], al[4+2*t+1], bh0, bh1);
                mma8(D, ah[2*t], ah[2*t+1], ah[4+2*t], ah[4+2*t+1], bl0, bl1);
            }
        }
    }

    // ---- epilogue 2: acc2 -> out (+fused bias) ----
    float* ob = out + (size_t)b * CCH * HW + h * WWW;
    #pragma unroll
    for (int t = 0; t < 2; ++t) {
        int r0 = mbase + 16 * t + g;
        #pragma unroll
        for (int nt = 0; nt < 4; ++nt) {
            int n0 = nt * 8 + tig * 2;
            int n1 = n0 + 1;
            if (n0 < CCH) {
                float bq = s_B2[n0];
                ob[(size_t)n0 * HW + r0]     = acc2[t][nt][0] + bq;
                ob[(size_t)n0 * HW + r0 + 8] = acc2[t][nt][2] + bq;
            }
            if (n1 < CCH) {
                float bq = s_B2[n1];
                ob[(size_t)n1 * HW + r0]     = acc2[t][nt][1] + bq;
                ob[(size_t)n1 * HW + r0 + 8] = acc2[t][nt][3] + bq;
            }
        }
    }
}

// ---------------------------------------------------------------------------
extern "C" void kernel_launch(void* const* d_in, const int* in_sizes, int n_in,
                              void* d_out, int out_size) {
    const float* x      = (const float*)d_in[0];
    const float* weight = (const float*)d_in[1];
    const float* bias   = (const float*)d_in[2];
    const float* w_t    = (const float*)d_in[3];
    const float* b_t    = (const float*)d_in[4];
    const float* w_m    = (const float*)d_in[5];
    const float* b_m    = (const float*)d_in[6];
    float* out = (float*)d_out;

    cudaFuncSetAttribute(harmonic_mma_kernel,
                         cudaFuncAttributeMaxDynamicSharedMemorySize, SMEM_BYTES);
    harmonic_mma_kernel<<<BBATCH * HHH, 256, SMEM_BYTES>>>(
        x, weight, bias, w_t, b_t, w_m, b_m, out);
}

// round 6
// speedup vs baseline: 1.3976x; 1.1761x over previous
#include <cuda_runtime.h>
#include <cstdint>

#define BBATCH 8
#define CCH    28
#define HHH    256
#define WWW    256
#define KHH    7
#define NGI    49
#define HW     (HHH*WWW)
#define PADH   3

// smem float-index layout
#define BF_OFF    0
#define BF_FLOATS (28*4*32*4)           // 14336 : [s][nt][lane] float4 (bh0,bh1,bl0,bl1)
#define MID_W     264                   // 3 halo + 256 + 5 halo ; 264%32==8 -> conflict-free
#define MID_OFF   BF_FLOATS             // 14336
#define MID_SIZE  (CCH*MID_W)           // 7392
#define STG_OFF   (MID_OFF+MID_SIZE)    // 21728 : 8 warps x 8 rows x 40
#define STG_SIZE  (8*8*40)              // 2560
#define TBL_OFF   (STG_OFF+STG_SIZE)    // 24288
#define SMEM_FLOATS (TBL_OFF + 56*5 + 64)
#define SMEM_BYTES  (SMEM_FLOATS*4)

static __device__ __forceinline__ void mma8(float* d,
                                            uint32_t a0, uint32_t a1,
                                            uint32_t a2, uint32_t a3,
                                            uint32_t b0, uint32_t b1) {
    asm volatile(
        "mma.sync.aligned.m16n8k8.row.col.f32.tf32.tf32.f32 "
        "{%0,%1,%2,%3}, {%4,%5,%6,%7}, {%8,%9}, {%0,%1,%2,%3};"
        : "+f"(d[0]), "+f"(d[1]), "+f"(d[2]), "+f"(d[3])
        : "r"(a0), "r"(a1), "r"(a2), "r"(a3), "r"(b0), "r"(b1));
}
static __device__ __forceinline__ void split(float v, uint32_t& h, uint32_t& l) {
    uint32_t hb = __float_as_uint(v) & 0xffffe000u;
    h = hb;
    l = __float_as_uint(v - __uint_as_float(hb));
}

__global__ void __launch_bounds__(256, 2)
harmonic_mma_kernel(const float* __restrict__ x,
                    const float* __restrict__ weight,
                    const float* __restrict__ bias,
                    const float* __restrict__ w_t,
                    const float* __restrict__ b_t,
                    const float* __restrict__ w_m,
                    const float* __restrict__ b_m,
                    float* __restrict__ out) {
    extern __shared__ float sm[];
    float* s_bf  = sm + BF_OFF;
    float* s_mid = sm + MID_OFF;
    float* s_stg = sm + STG_OFF;
    float* s_f0  = sm + TBL_OFF;
    float* s_f1  = s_f0 + 56;
    int*   s_y0  = (int*)(s_f1 + 56);
    int*   s_y1  = s_y0 + 56;
    int*   s_pl  = s_y1 + 56;
    float* s_b1  = (float*)(s_pl + 56);
    float* s_B2  = s_b1 + 28;

    const int tid  = threadIdx.x;
    const int wid  = tid >> 5;
    const int lane = tid & 31;
    const int g    = lane >> 2;
    const int tig  = lane & 3;
    const int h    = blockIdx.x & 255;
    const int b    = blockIdx.x >> 8;
    const int mbase = wid * 32;
    const int m0    = mbase + g;

    // ---- per-h harmonic tables ----
    if (tid < NGI) {
        int gg = tid / KHH, ii = tid % KHH;
        float fh = (float)h, fg = (float)gg, fi = (float)ii;
        float t   = __fdiv_rn(fh + 1.0f, fg + 1.0f) * (fi + 1.0f);
        float off = -fi + t - (fh + 1.0f);
        float yp  = fh - (float)PADH + fi + off;
        float y0f = floorf(yp);
        float fy  = yp - y0f;
        int   y0i = (int)y0f;
        float v0 = (y0i >= 0 && y0i <= HHH - 1) ? 1.0f : 0.0f;
        float v1 = (y0i + 1 >= 0 && y0i + 1 <= HHH - 1) ? 1.0f : 0.0f;
        int y0c = y0i < 0 ? 0 : (y0i > HHH - 1 ? HHH - 1 : y0i);
        int y1i = y0i + 1;
        int y1c = y1i < 0 ? 0 : (y1i > HHH - 1 ? HHH - 1 : y1i);
        s_y0[tid] = y0c * WWW;
        s_y1[tid] = y1c * WWW;
        s_f0[tid] = (1.0f - fy) * v0;
        s_f1[tid] = fy * v1;
        s_pl[tid] = (tid / KHH) * 4;
    }
    if (tid < CCH) {
        s_b1[tid] = bias[tid];
        int f = tid >> 2, cq = tid & 3;
        float s = b_m[f];
        #pragma unroll
        for (int g7 = 0; g7 < 7; ++g7) s += w_m[f * 7 + g7] * b_t[g7 * 4 + cq];
        s_B2[tid] = s;
    }

    // ---- B1 fragments: k = gi*4 + c ; float4 (bh0,bh1,bl0,bl1) ----
    for (int idx = tid; idx < 3584; idx += 256) {
        int s  = idx >> 7;
        int ln = idx & 31;
        int n  = ((idx >> 5) & 3) * 8 + (ln >> 2);
        int tt = ln & 3;
        float v0 = 0.0f, v1 = 0.0f;
        int k0 = 8 * s + tt, k1 = k0 + 4;
        int gia = k0 >> 2, ca = k0 & 3, gib = k1 >> 2, cb = k1 & 3;
        if (n < CCH && gia < NGI)
            v0 = weight[(n * CCH + (gia / KHH) * 4 + ca) * KHH + (gia % KHH)];
        if (n < CCH && gib < NGI)
            v1 = weight[(n * CCH + (gib / KHH) * 4 + cb) * KHH + (gib % KHH)];
        uint32_t h0, l0, h1, l1;
        split(v0, h0, l0);
        split(v1, h1, l1);
        ((float4*)s_bf)[idx] = make_float4(__uint_as_float(h0), __uint_as_float(h1),
                                           __uint_as_float(l0), __uint_as_float(l1));
    }
    __syncthreads();

    const float* xb = x + (size_t)b * CCH * HW;
    float* stg = s_stg + wid * 320;

    // =================== STAGE 1 ===================
    float acc[2][4][4];
    #pragma unroll
    for (int t = 0; t < 2; ++t)
        #pragma unroll
        for (int nt = 0; nt < 4; ++nt)
            #pragma unroll
            for (int r = 0; r < 4; ++r) acc[t][nt][r] = 0.0f;

    #pragma unroll 2
    for (int s = 0; s < 28; ++s) {
        int gi0 = 2 * s;     if (gi0 > 48) gi0 = 48;
        int gi1 = 2 * s + 1; if (gi1 > 48) gi1 = 48;
        float vv[8];
        #pragma unroll
        for (int tp = 0; tp < 2; ++tp) {
            const int gi = tp ? gi1 : gi0;
            const int o0 = s_y0[gi], o1 = s_y1[gi];
            const float f0 = s_f0[gi], f1 = s_f1[gi];
            const float* pp = xb + (size_t)s_pl[gi] * HW + mbase + lane;
            #pragma unroll
            for (int c = 0; c < 4; ++c) {
                float a0 = __ldg(pp + c * HW + o0);
                float a1 = __ldg(pp + c * HW + o1);
                vv[tp * 4 + c] = a0 * f0 + a1 * f1;
            }
        }
        #pragma unroll
        for (int r = 0; r < 8; ++r) stg[r * 40 + lane] = vv[r];
        __syncwarp();
        uint32_t ah[8], al[8];
        #pragma unroll
        for (int q = 0; q < 4; ++q) {
            split(stg[tig * 40 + 8 * q + g], ah[q], al[q]);
            split(stg[(4 + tig) * 40 + 8 * q + g], ah[4 + q], al[4 + q]);
        }
        __syncwarp();

        const float4* bf4 = (const float4*)s_bf + s * 128 + lane;
        #pragma unroll
        for (int nt = 0; nt < 4; ++nt) {
            float4 bv = bf4[nt * 32];
            uint32_t bh0 = __float_as_uint(bv.x), bh1 = __float_as_uint(bv.y);
            uint32_t bl0 = __float_as_uint(bv.z), bl1 = __float_as_uint(bv.w);
            #pragma unroll
            for (int t = 0; t < 2; ++t) {
                float* D = acc[t][nt];
                mma8(D, ah[2*t], ah[2*t+1], ah[4+2*t], ah[4+2*t+1], bh0, bh1);
                mma8(D, al[2*t], al[2*t+1], al[4+2*t], al[4+2*t+1], bh0, bh1);
                mma8(D, ah[2*t], ah[2*t+1], ah[4+2*t], ah[4+2*t+1], bl0, bl1);
            }
        }
    }

    // ---- epilogue 1: acc -> mid (+bias) ----
    #pragma unroll
    for (int t = 0; t < 2; ++t) {
        int r0 = mbase + 16 * t + g;
        #pragma unroll
        for (int nt = 0; nt < 4; ++nt) {
            int n0 = nt * 8 + tig * 2;
            int n1 = n0 + 1;
            if (n0 < CCH) {
                float bq = s_b1[n0];
                s_mid[n0 * MID_W + 3 + r0]     = acc[t][nt][0] + bq;
                s_mid[n0 * MID_W + 3 + r0 + 8] = acc[t][nt][2] + bq;
            }
            if (n1 < CCH) {
                float bq = s_b1[n1];
                s_mid[n1 * MID_W + 3 + r0]     = acc[t][nt][1] + bq;
                s_mid[n1 * MID_W + 3 + r0 + 8] = acc[t][nt][3] + bq;
            }
        }
    }
    if (tid < 224) {   // halo zeros: cols 0..2 and 259..263
        int i = tid >> 3, p = tid & 7;
        int col = (p < 3) ? p : 256 + p;
        s_mid[i * MID_W + col] = 0.0f;
    }
    __syncthreads();

    // ---- B2 fragments: k = j*32 + i (fused conv1x7 ∘ group-mix) ----
    for (int idx = tid; idx < 3584; idx += 256) {
        int s  = idx >> 7;
        int ln = idx & 31;
        int n  = ((idx >> 5) & 3) * 8 + (ln >> 2);
        int tt = ln & 3;
        int k0 = 8 * s + tt;
        int j  = k0 >> 5;
        int i0 = k0 & 31, i1 = i0 + 4;
        float v0 = 0.0f, v1 = 0.0f;
        if (n < CCH) {
            int f = n >> 2, cq = n & 3;
            #pragma unroll
            for (int g7 = 0; g7 < 7; ++g7) {
                float wm = w_m[f * 7 + g7];
                int base = (g7 * 4 + cq) * CCH;
                if (i0 < CCH) v0 += wm * w_t[(base + i0) * KHH + j];
                if (i1 < CCH) v1 += wm * w_t[(base + i1) * KHH + j];
            }
        }
        uint32_t h0, l0, h1, l1;
        split(v0, h0, l0);
        split(v1, h1, l1);
        ((float4*)s_bf)[idx] = make_float4(__uint_as_float(h0), __uint_as_float(h1),
                                           __uint_as_float(l0), __uint_as_float(l1));
    }
    __syncthreads();

    // =================== STAGE 2 ===================
    float acc2[2][4][4];
    #pragma unroll
    for (int t = 0; t < 2; ++t)
        #pragma unroll
        for (int nt = 0; nt < 4; ++nt)
            #pragma unroll
            for (int r = 0; r < 4; ++r) acc2[t][nt][r] = 0.0f;

    #pragma unroll 2
    for (int s = 0; s < 28; ++s) {
        const int jj = s >> 2;
        const int ib = (s & 3) * 8;
        const float* mra = s_mid + (ib + tig) * MID_W + m0 + jj;
        const float* mrb = s_mid + (ib + tig + 4) * MID_W + m0 + jj;
        uint32_t ah[8], al[8];
        #pragma unroll
        for (int q = 0; q < 4; ++q) {
            split(mra[8 * q], ah[q], al[q]);
            split(mrb[8 * q], ah[4 + q], al[4 + q]);
        }
        const float4* bf4 = (const float4*)s_bf + s * 128 + lane;
        #pragma unroll
        for (int nt = 0; nt < 4; ++nt) {
            float4 bv = bf4[nt * 32];
            uint32_t bh0 = __float_as_uint(bv.x), bh1 = __float_as_uint(bv.y);
            uint32_t bl0 = __float_as_uint(bv.z), bl1 = __float_as_uint(bv.w);
            #pragma unroll
            for (int t = 0; t < 2; ++t) {
                float* D = acc2[t][nt];
                mma8(D, ah[2*t], ah[2*t+1], ah[4+2*t], ah[4+2*t+1], bh0, bh1);
                mma8(D, al[2*t], al[2*t+1], al[4+2*t], al[4+2*t+1], bh0, bh1);
                mma8(D, ah[2*t], ah[2*t+1], ah[4+2*t], ah[4+2*t+1], bl0, bl1);
            }
        }
    }

    // ---- epilogue 2: acc2 -> out (+fused bias) ----
    float* ob = out + (size_t)b * CCH * HW + h * WWW;
    #pragma unroll
    for (int t = 0; t < 2; ++t) {
        int r0 = mbase + 16 * t + g;
        #pragma unroll
        for (int nt = 0; nt < 4; ++nt) {
            int n0 = nt * 8 + tig * 2;
            int n1 = n0 + 1;
            if (n0 < CCH) {
                float bq = s_B2[n0];
                ob[(size_t)n0 * HW + r0]     = acc2[t][nt][0] + bq;
                ob[(size_t)n0 * HW + r0 + 8] = acc2[t][nt][2] + bq;
            }
            if (n1 < CCH) {
                float bq = s_B2[n1];
                ob[(size_t)n1 * HW + r0]     = acc2[t][nt][1] + bq;
                ob[(size_t)n1 * HW + r0 + 8] = acc2[t][nt][3] + bq;
            }
        }
    }
}

// ---------------------------------------------------------------------------
extern "C" void kernel_launch(void* const* d_in, const int* in_sizes, int n_in,
                              void* d_out, int out_size) {
    const float* x      = (const float*)d_in[0];
    const float* weight = (const float*)d_in[1];
    const float* bias   = (const float*)d_in[2];
    const float* w_t    = (const float*)d_in[3];
    const float* b_t    = (const float*)d_in[4];
    const float* w_m    = (const float*)d_in[5];
    const float* b_m    = (const float*)d_in[6];
    float* out = (float*)d_out;

    cudaFuncSetAttribute(harmonic_mma_kernel,
                         cudaFuncAttributeMaxDynamicSharedMemorySize, SMEM_BYTES);
    harmonic_mma_kernel<<<BBATCH * HHH, 256, SMEM_BYTES>>>(
        x, weight, bias, w_t, b_t, w_m, b_m, out);
}

// round 7
// speedup vs baseline: 1.6638x; 1.1905x over previous
#include <cuda_runtime.h>
#include <cstdint>

#define BBATCH 8
#define CCH    28
#define HHH    256
#define WWW    256
#define KHH    7
#define NGI    49
#define HW     (HHH*WWW)
#define PADH   3

// smem float-index layout
#define BF_OFF    0
#define BF_FLOATS (28*4*32*2)           // 7168 : [s][nt][lane] float2 (bh0,bh1)
#define MID_W     264                   // 3 halo + 256 + 5 halo ; 264%32==8
#define MID_OFF   BF_FLOATS
#define MID_SIZE  (CCH*MID_W)           // 7392
#define STG_OFF   (MID_OFF+MID_SIZE)    // 14560 : 8 warps x 8 rows x 40
#define STG_SIZE  (8*8*40)              // 2560
#define TBL_OFF   (STG_OFF+STG_SIZE)    // 17120
#define SMEM_FLOATS (TBL_OFF + 56*5 + 64)
#define SMEM_BYTES  (SMEM_FLOATS*4)

static __device__ __forceinline__ void mma8(float* d,
                                            uint32_t a0, uint32_t a1,
                                            uint32_t a2, uint32_t a3,
                                            uint32_t b0, uint32_t b1) {
    asm volatile(
        "mma.sync.aligned.m16n8k8.row.col.f32.tf32.tf32.f32 "
        "{%0,%1,%2,%3}, {%4,%5,%6,%7}, {%8,%9}, {%0,%1,%2,%3};"
        : "+f"(d[0]), "+f"(d[1]), "+f"(d[2]), "+f"(d[3])
        : "r"(a0), "r"(a1), "r"(a2), "r"(a3), "r"(b0), "r"(b1));
}
static __device__ __forceinline__ void split(float v, uint32_t& h, uint32_t& l) {
    uint32_t hb = __float_as_uint(v) & 0xffffe000u;
    h = hb;
    l = __float_as_uint(v - __uint_as_float(hb));
}
// rna-rounded tf32 (for B-hi: minimizes the dropped residual)
static __device__ __forceinline__ float tf32rna(float v) {
    uint32_t r;
    asm("cvt.rna.tf32.f32 %0, %1;" : "=r"(r) : "f"(v));
    return __uint_as_float(r);
}

__global__ void __launch_bounds__(256, 3)
harmonic_mma_kernel(const float* __restrict__ x,
                    const float* __restrict__ weight,
                    const float* __restrict__ bias,
                    const float* __restrict__ w_t,
                    const float* __restrict__ b_t,
                    const float* __restrict__ w_m,
                    const float* __restrict__ b_m,
                    float* __restrict__ out) {
    extern __shared__ float sm[];
    float* s_bf  = sm + BF_OFF;
    float* s_mid = sm + MID_OFF;
    float* s_stg = sm + STG_OFF;
    float* s_f0  = sm + TBL_OFF;
    float* s_f1  = s_f0 + 56;
    int*   s_y0  = (int*)(s_f1 + 56);
    int*   s_y1  = s_y0 + 56;
    int*   s_pl  = s_y1 + 56;
    float* s_b1  = (float*)(s_pl + 56);
    float* s_B2  = s_b1 + 28;

    const int tid  = threadIdx.x;
    const int wid  = tid >> 5;
    const int lane = tid & 31;
    const int g    = lane >> 2;
    const int tig  = lane & 3;
    const int h    = blockIdx.x & 255;
    const int b    = blockIdx.x >> 8;
    const int mbase = wid * 32;
    const int m0    = mbase + g;

    // ---- per-h harmonic tables ----
    if (tid < NGI) {
        int gg = tid / KHH, ii = tid % KHH;
        float fh = (float)h, fg = (float)gg, fi = (float)ii;
        float t   = __fdiv_rn(fh + 1.0f, fg + 1.0f) * (fi + 1.0f);
        float off = -fi + t - (fh + 1.0f);
        float yp  = fh - (float)PADH + fi + off;
        float y0f = floorf(yp);
        float fy  = yp - y0f;
        int   y0i = (int)y0f;
        float v0 = (y0i >= 0 && y0i <= HHH - 1) ? 1.0f : 0.0f;
        float v1 = (y0i + 1 >= 0 && y0i + 1 <= HHH - 1) ? 1.0f : 0.0f;
        int y0c = y0i < 0 ? 0 : (y0i > HHH - 1 ? HHH - 1 : y0i);
        int y1i = y0i + 1;
        int y1c = y1i < 0 ? 0 : (y1i > HHH - 1 ? HHH - 1 : y1i);
        s_y0[tid] = y0c * WWW;
        s_y1[tid] = y1c * WWW;
        s_f0[tid] = (1.0f - fy) * v0;
        s_f1[tid] = fy * v1;
        s_pl[tid] = (tid / KHH) * 4;
    }
    if (tid < CCH) {
        s_b1[tid] = bias[tid];
        int f = tid >> 2, cq = tid & 3;
        float s = b_m[f];
        #pragma unroll
        for (int g7 = 0; g7 < 7; ++g7) s += w_m[f * 7 + g7] * b_t[g7 * 4 + cq];
        s_B2[tid] = s;
    }

    // ---- B1 fragments: k = gi*4 + c ; float2 (bh0,bh1), rna-rounded ----
    for (int idx = tid; idx < 3584; idx += 256) {
        int s  = idx >> 7;
        int ln = idx & 31;
        int n  = ((idx >> 5) & 3) * 8 + (ln >> 2);
        int tt = ln & 3;
        float v0 = 0.0f, v1 = 0.0f;
        int k0 = 8 * s + tt, k1 = k0 + 4;
        int gia = k0 >> 2, ca = k0 & 3, gib = k1 >> 2, cb = k1 & 3;
        if (n < CCH && gia < NGI)
            v0 = weight[(n * CCH + (gia / KHH) * 4 + ca) * KHH + (gia % KHH)];
        if (n < CCH && gib < NGI)
            v1 = weight[(n * CCH + (gib / KHH) * 4 + cb) * KHH + (gib % KHH)];
        ((float2*)s_bf)[idx] = make_float2(tf32rna(v0), tf32rna(v1));
    }
    __syncthreads();

    const float* xb = x + (size_t)b * CCH * HW;
    float* stg = s_stg + wid * 320;

    // =================== STAGE 1 ===================
    float acc[2][4][4];
    #pragma unroll
    for (int t = 0; t < 2; ++t)
        #pragma unroll
        for (int nt = 0; nt < 4; ++nt)
            #pragma unroll
            for (int r = 0; r < 4; ++r) acc[t][nt][r] = 0.0f;

    #pragma unroll 2
    for (int s = 0; s < 28; ++s) {
        int gi0 = 2 * s;     if (gi0 > 48) gi0 = 48;
        int gi1 = 2 * s + 1; if (gi1 > 48) gi1 = 48;
        float vv[8];
        #pragma unroll
        for (int tp = 0; tp < 2; ++tp) {
            const int gi = tp ? gi1 : gi0;
            const int o0 = s_y0[gi], o1 = s_y1[gi];
            const float f0 = s_f0[gi], f1 = s_f1[gi];
            const float* pp = xb + (size_t)s_pl[gi] * HW + mbase + lane;
            #pragma unroll
            for (int c = 0; c < 4; ++c) {
                float a0 = __ldg(pp + c * HW + o0);
                float a1 = __ldg(pp + c * HW + o1);
                vv[tp * 4 + c] = a0 * f0 + a1 * f1;
            }
        }
        #pragma unroll
        for (int r = 0; r < 8; ++r) stg[r * 40 + lane] = vv[r];
        __syncwarp();
        uint32_t ah[8], al[8];
        #pragma unroll
        for (int q = 0; q < 4; ++q) {
            split(stg[tig * 40 + 8 * q + g], ah[q], al[q]);
            split(stg[(4 + tig) * 40 + 8 * q + g], ah[4 + q], al[4 + q]);
        }
        __syncwarp();

        const float2* bf2 = (const float2*)s_bf + s * 128 + lane;
        #pragma unroll
        for (int nt = 0; nt < 4; ++nt) {
            float2 bv = bf2[nt * 32];
            uint32_t bh0 = __float_as_uint(bv.x), bh1 = __float_as_uint(bv.y);
            #pragma unroll
            for (int t = 0; t < 2; ++t) {
                float* D = acc[t][nt];
                mma8(D, ah[2*t], ah[2*t+1], ah[4+2*t], ah[4+2*t+1], bh0, bh1);
                mma8(D, al[2*t], al[2*t+1], al[4+2*t], al[4+2*t+1], bh0, bh1);
            }
        }
    }

    // ---- epilogue 1: acc -> mid (+bias) ----
    #pragma unroll
    for (int t = 0; t < 2; ++t) {
        int r0 = mbase + 16 * t + g;
        #pragma unroll
        for (int nt = 0; nt < 4; ++nt) {
            int n0 = nt * 8 + tig * 2;
            int n1 = n0 + 1;
            if (n0 < CCH) {
                float bq = s_b1[n0];
                s_mid[n0 * MID_W + 3 + r0]     = acc[t][nt][0] + bq;
                s_mid[n0 * MID_W + 3 + r0 + 8] = acc[t][nt][2] + bq;
            }
            if (n1 < CCH) {
                float bq = s_b1[n1];
                s_mid[n1 * MID_W + 3 + r0]     = acc[t][nt][1] + bq;
                s_mid[n1 * MID_W + 3 + r0 + 8] = acc[t][nt][3] + bq;
            }
        }
    }
    if (tid < 224) {   // halo zeros: cols 0..2 and 259..263
        int i = tid >> 3, p = tid & 7;
        int col = (p < 3) ? p : 256 + p;
        s_mid[i * MID_W + col] = 0.0f;
    }
    __syncthreads();

    // ---- B2 fragments: k = j*32 + i (fused conv1x7 ∘ group-mix) ----
    for (int idx = tid; idx < 3584; idx += 256) {
        int s  = idx >> 7;
        int ln = idx & 31;
        int n  = ((idx >> 5) & 3) * 8 + (ln >> 2);
        int tt = ln & 3;
        int k0 = 8 * s + tt;
        int j  = k0 >> 5;
        int i0 = k0 & 31, i1 = i0 + 4;
        float v0 = 0.0f, v1 = 0.0f;
        if (n < CCH) {
            int f = n >> 2, cq = n & 3;
            #pragma unroll
            for (int g7 = 0; g7 < 7; ++g7) {
                float wm = w_m[f * 7 + g7];
                int base = (g7 * 4 + cq) * CCH;
                if (i0 < CCH) v0 += wm * w_t[(base + i0) * KHH + j];
                if (i1 < CCH) v1 += wm * w_t[(base + i1) * KHH + j];
            }
        }
        ((float2*)s_bf)[idx] = make_float2(tf32rna(v0), tf32rna(v1));
    }
    __syncthreads();

    // =================== STAGE 2 ===================
    float acc2[2][4][4];
    #pragma unroll
    for (int t = 0; t < 2; ++t)
        #pragma unroll
        for (int nt = 0; nt < 4; ++nt)
            #pragma unroll
            for (int r = 0; r < 4; ++r) acc2[t][nt][r] = 0.0f;

    #pragma unroll 2
    for (int s = 0; s < 28; ++s) {
        const int jj = s >> 2;
        const int ib = (s & 3) * 8;
        const float* mra = s_mid + (ib + tig) * MID_W + m0 + jj;
        const float* mrb = s_mid + (ib + tig + 4) * MID_W + m0 + jj;
        uint32_t ah[8], al[8];
        #pragma unroll
        for (int q = 0; q < 4; ++q) {
            split(mra[8 * q], ah[q], al[q]);
            split(mrb[8 * q], ah[4 + q], al[4 + q]);
        }
        const float2* bf2 = (const float2*)s_bf + s * 128 + lane;
        #pragma unroll
        for (int nt = 0; nt < 4; ++nt) {
            float2 bv = bf2[nt * 32];
            uint32_t bh0 = __float_as_uint(bv.x), bh1 = __float_as_uint(bv.y);
            #pragma unroll
            for (int t = 0; t < 2; ++t) {
                float* D = acc2[t][nt];
                mma8(D, ah[2*t], ah[2*t+1], ah[4+2*t], ah[4+2*t+1], bh0, bh1);
                mma8(D, al[2*t], al[2*t+1], al[4+2*t], al[4+2*t+1], bh0, bh1);
            }
        }
    }

    // ---- epilogue 2: acc2 -> out (+fused bias) ----
    float* ob = out + (size_t)b * CCH * HW + h * WWW;
    #pragma unroll
    for (int t = 0; t < 2; ++t) {
        int r0 = mbase + 16 * t + g;
        #pragma unroll
        for (int nt = 0; nt < 4; ++nt) {
            int n0 = nt * 8 + tig * 2;
            int n1 = n0 + 1;
            if (n0 < CCH) {
                float bq = s_B2[n0];
                ob[(size_t)n0 * HW + r0]     = acc2[t][nt][0] + bq;
                ob[(size_t)n0 * HW + r0 + 8] = acc2[t][nt][2] + bq;
            }
            if (n1 < CCH) {
                float bq = s_B2[n1];
                ob[(size_t)n1 * HW + r0]     = acc2[t][nt][1] + bq;
                ob[(size_t)n1 * HW + r0 + 8] = acc2[t][nt][3] + bq;
            }
        }
    }
}

// ---------------------------------------------------------------------------
extern "C" void kernel_launch(void* const* d_in, const int* in_sizes, int n_in,
                              void* d_out, int out_size) {
    const float* x      = (const float*)d_in[0];
    const float* weight = (const float*)d_in[1];
    const float* bias   = (const float*)d_in[2];
    const float* w_t    = (const float*)d_in[3];
    const float* b_t    = (const float*)d_in[4];
    const float* w_m    = (const float*)d_in[5];
    const float* b_m    = (const float*)d_in[6];
    float* out = (float*)d_out;

    cudaFuncSetAttribute(harmonic_mma_kernel,
                         cudaFuncAttributeMaxDynamicSharedMemorySize, SMEM_BYTES);
    harmonic_mma_kernel<<<BBATCH * HHH, 256, SMEM_BYTES>>>(
        x, weight, bias, w_t, b_t, w_m, b_m, out);
}

// round 8
// speedup vs baseline: 2.0217x; 1.2151x over previous
#include <cuda_runtime.h>
#include <cuda_fp16.h>
#include <cstdint>

#define BBATCH 8
#define CCH    28
#define HHH    256
#define WWW    256
#define KHH    7
#define NGI    49
#define HW     (HHH*WWW)
#define PADH   3

// smem u32-index layout
#define BF_OFF    0                    // 14 steps x 4 nt x 32 lanes x uint2 = 3584 u32
#define BF_U32    3584
#define MIDH_OFF  (BF_OFF+BF_U32)      // 16 pair-rows x 264 = 4224
#define MIDL_OFF  (MIDH_OFF+4224)      // 4224
#define STG_OFF   (MIDL_OFF+4224)      // 8 warps x (hi 320 + lo 320) = 5120
#define TBL_OFF   (STG_OFF+5120)       // tables
#define SMEM_U32  (TBL_OFF + 56*5 + 64)
#define SMEM_BYTES (SMEM_U32*4)

static __device__ __forceinline__ void mma16(float* d,
                                             uint32_t a0, uint32_t a1,
                                             uint32_t a2, uint32_t a3,
                                             uint32_t b0, uint32_t b1) {
    asm volatile(
        "mma.sync.aligned.m16n8k16.row.col.f32.f16.f16.f32 "
        "{%0,%1,%2,%3}, {%4,%5,%6,%7}, {%8,%9}, {%0,%1,%2,%3};"
        : "+f"(d[0]), "+f"(d[1]), "+f"(d[2]), "+f"(d[3])
        : "r"(a0), "r"(a1), "r"(a2), "r"(a3), "r"(b0), "r"(b1));
}
static __device__ __forceinline__ uint32_t h2u(__half2 h) {
    return *reinterpret_cast<uint32_t*>(&h);
}
// pack (a,b) to f16x2 hi and residual lo
static __device__ __forceinline__ void packhl(float a, float b,
                                              uint32_t& hi, uint32_t& lo) {
    __half2 h = __floats2half2_rn(a, b);
    float2 hf = __half22float2(h);
    __half2 l = __floats2half2_rn(a - hf.x, b - hf.y);
    hi = h2u(h);
    lo = h2u(l);
}

__global__ void __launch_bounds__(256, 3)
harmonic_mma_kernel(const float* __restrict__ x,
                    const float* __restrict__ weight,
                    const float* __restrict__ bias,
                    const float* __restrict__ w_t,
                    const float* __restrict__ b_t,
                    const float* __restrict__ w_m,
                    const float* __restrict__ b_m,
                    float* __restrict__ out) {
    extern __shared__ uint32_t smu[];
    uint32_t* s_bf   = smu + BF_OFF;
    uint32_t* s_mhi  = smu + MIDH_OFF;
    uint32_t* s_mlo  = smu + MIDL_OFF;
    uint32_t* s_stg  = smu + STG_OFF;
    float*    s_f0   = (float*)(smu + TBL_OFF);
    float*    s_f1   = s_f0 + 56;
    int*      s_y0   = (int*)(s_f1 + 56);
    int*      s_y1   = s_y0 + 56;
    int*      s_pl   = s_y1 + 56;
    float*    s_b1   = (float*)(s_pl + 56);   // 32 (28..31 zero)
    float*    s_B2   = s_b1 + 32;             // 32

    const int tid  = threadIdx.x;
    const int wid  = tid >> 5;
    const int lane = tid & 31;
    const int g    = lane >> 2;
    const int tig  = lane & 3;
    const int h    = blockIdx.x & 255;
    const int b    = blockIdx.x >> 8;
    const int mbase = wid * 32;

    // ---- per-h harmonic tables ----
    if (tid < NGI) {
        int gg = tid / KHH, ii = tid % KHH;
        float fh = (float)h, fg = (float)gg, fi = (float)ii;
        float t   = __fdiv_rn(fh + 1.0f, fg + 1.0f) * (fi + 1.0f);
        float off = -fi + t - (fh + 1.0f);
        float yp  = fh - (float)PADH + fi + off;
        float y0f = floorf(yp);
        float fy  = yp - y0f;
        int   y0i = (int)y0f;
        float v0 = (y0i >= 0 && y0i <= HHH - 1) ? 1.0f : 0.0f;
        float v1 = (y0i + 1 >= 0 && y0i + 1 <= HHH - 1) ? 1.0f : 0.0f;
        int y0c = y0i < 0 ? 0 : (y0i > HHH - 1 ? HHH - 1 : y0i);
        int y1i = y0i + 1;
        int y1c = y1i < 0 ? 0 : (y1i > HHH - 1 ? HHH - 1 : y1i);
        s_y0[tid] = y0c * WWW;
        s_y1[tid] = y1c * WWW;
        s_f0[tid] = (1.0f - fy) * v0;
        s_f1[tid] = fy * v1;
        s_pl[tid] = (tid / KHH) * 4;
    }
    if (tid < 32) {
        s_b1[tid] = (tid < CCH) ? bias[tid] : 0.0f;
        float s = 0.0f;
        if (tid < CCH) {
            int f = tid >> 2, cq = tid & 3;
            s = b_m[f];
            #pragma unroll
            for (int g7 = 0; g7 < 7; ++g7) s += w_m[f * 7 + g7] * b_t[g7 * 4 + cq];
        }
        s_B2[tid] = s;
    }
    // mid halo zeros: 16 pair-rows x 8 cols, both planes
    if (tid < 128) {
        int p = tid >> 3, c8 = tid & 7;
        int col = (c8 < 3) ? c8 : 256 + c8;
        s_mhi[p * 264 + col] = 0u;
        s_mlo[p * 264 + col] = 0u;
    }

    // ---- B1 fragments: [s][nt][lane] uint2 (b0 = k-pair 2tig, b1 = 2tig+8) ----
    for (int idx = tid; idx < 1792; idx += 256) {
        int s  = idx >> 7;
        int nt = (idx >> 5) & 3;
        int ln = idx & 31;
        int n  = nt * 8 + (ln >> 2);
        int tt = ln & 3;
        int k0 = 16 * s + 2 * tt;
        float w4[4];
        #pragma unroll
        for (int e = 0; e < 4; ++e) {
            int k = k0 + (e & 1) + 8 * (e >> 1);
            float v = 0.0f;
            if (n < CCH && k < 196) {
                int gi = k >> 2, c = k & 3;
                v = weight[(n * CCH + (gi / KHH) * 4 + c) * KHH + (gi % KHH)];
            }
            w4[e] = v;
        }
        ((uint2*)s_bf)[idx] = make_uint2(h2u(__floats2half2_rn(w4[0], w4[1])),
                                        h2u(__floats2half2_rn(w4[2], w4[3])));
    }
    __syncthreads();

    const float* xb = x + (size_t)b * CCH * HW;
    uint32_t* stgh = s_stg + wid * 640;
    uint32_t* stgl = stgh + 320;

    float acc[2][4][4];
    #pragma unroll
    for (int t = 0; t < 2; ++t)
        #pragma unroll
        for (int nt = 0; nt < 4; ++nt)
            #pragma unroll
            for (int r = 0; r < 4; ++r) acc[t][nt][r] = 0.0f;

    // =================== STAGE 1 : 14 k16 steps ===================
    #pragma unroll 1
    for (int s = 0; s < 14; ++s) {
        #pragma unroll
        for (int r = 0; r < 2; ++r) {
            int gi0 = 4 * s + 2 * r; if (gi0 > 48) gi0 = 48;
            int gi1 = gi0 + 1;       if (gi1 > 48) gi1 = 48;
            float vv[8];
            #pragma unroll
            for (int tp = 0; tp < 2; ++tp) {
                const int gi = tp ? gi1 : gi0;
                const int o0 = s_y0[gi], o1 = s_y1[gi];
                const float f0 = s_f0[gi], f1 = s_f1[gi];
                const float* pp = xb + (size_t)s_pl[gi] * HW + mbase + lane;
                #pragma unroll
                for (int c = 0; c < 4; ++c) {
                    float a0 = __ldg(pp + c * HW + o0);
                    float a1 = __ldg(pp + c * HW + o1);
                    vv[tp * 4 + c] = a0 * f0 + a1 * f1;
                }
            }
            #pragma unroll
            for (int tp = 0; tp < 2; ++tp) {
                uint32_t h01, l01, h23, l23;
                packhl(vv[4 * tp + 0], vv[4 * tp + 1], h01, l01);
                packhl(vv[4 * tp + 2], vv[4 * tp + 3], h23, l23);
                int kp = 4 * r + 2 * tp;
                stgh[kp * 40 + lane]       = h01;
                stgh[(kp + 1) * 40 + lane] = h23;
                stgl[kp * 40 + lane]       = l01;
                stgl[(kp + 1) * 40 + lane] = l23;
            }
        }
        __syncwarp();

        uint32_t ahi[2][4], alo[2][4];
        #pragma unroll
        for (int t = 0; t < 2; ++t) {
            int mb2 = 16 * t + g;
            ahi[t][0] = stgh[tig * 40 + mb2];
            ahi[t][1] = stgh[tig * 40 + mb2 + 8];
            ahi[t][2] = stgh[(tig + 4) * 40 + mb2];
            ahi[t][3] = stgh[(tig + 4) * 40 + mb2 + 8];
            alo[t][0] = stgl[tig * 40 + mb2];
            alo[t][1] = stgl[tig * 40 + mb2 + 8];
            alo[t][2] = stgl[(tig + 4) * 40 + mb2];
            alo[t][3] = stgl[(tig + 4) * 40 + mb2 + 8];
        }
        __syncwarp();

        const uint2* bfp = (const uint2*)s_bf + s * 128 + lane;
        #pragma unroll
        for (int nt = 0; nt < 4; ++nt) {
            uint2 bv = bfp[nt * 32];
            #pragma unroll
            for (int t = 0; t < 2; ++t) {
                mma16(acc[t][nt], ahi[t][0], ahi[t][1], ahi[t][2], ahi[t][3], bv.x, bv.y);
                mma16(acc[t][nt], alo[t][0], alo[t][1], alo[t][2], alo[t][3], bv.x, bv.y);
            }
        }
    }

    // ---- epilogue 1: acc -> mid pair planes (+bias, hi/lo split) ----
    #pragma unroll
    for (int t = 0; t < 2; ++t) {
        #pragma unroll
        for (int nt = 0; nt < 2; ++nt) {
            #pragma unroll
            for (int r = 0; r < 4; ++r) {
                int n   = nt * 8 + 2 * tig + (r & 1);
                int row = mbase + 16 * t + g + 8 * (r >> 1);
                float va = acc[t][nt][r]     + s_b1[n];
                float vb = acc[t][nt + 2][r] + s_b1[n + 16];
                uint32_t hi, lo;
                packhl(va, vb, hi, lo);
                s_mhi[n * 264 + 3 + row] = hi;
                s_mlo[n * 264 + 3 + row] = lo;
            }
        }
    }
    __syncthreads();

    // ---- B2 fragments: k = j*32 + kk, i = (kk>>1) + 16*(kk&1) ----
    for (int idx = tid; idx < 1792; idx += 256) {
        int s  = idx >> 7;
        int nt = (idx >> 5) & 3;
        int ln = idx & 31;
        int n  = nt * 8 + (ln >> 2);
        int tt = ln & 3;
        int j  = s >> 1;
        int ie = 8 * (s & 1) + tt;     // i for k-even of b0
        float w4[4];
        #pragma unroll
        for (int e = 0; e < 4; ++e) {
            int i2 = ie + 4 * (e >> 1) + 16 * (e & 1);
            float v = 0.0f;
            if (n < CCH && i2 < CCH) {
                int f = n >> 2, cq = n & 3;
                #pragma unroll
                for (int g7 = 0; g7 < 7; ++g7)
                    v += w_m[f * 7 + g7] * w_t[((g7 * 4 + cq) * CCH + i2) * KHH + j];
            }
            w4[e] = v;
        }
        ((uint2*)s_bf)[idx] = make_uint2(h2u(__floats2half2_rn(w4[0], w4[1])),
                                        h2u(__floats2half2_rn(w4[2], w4[3])));
    }
    // reset accumulators
    #pragma unroll
    for (int t = 0; t < 2; ++t)
        #pragma unroll
        for (int nt = 0; nt < 4; ++nt)
            #pragma unroll
            for (int r = 0; r < 4; ++r) acc[t][nt][r] = 0.0f;
    __syncthreads();

    // =================== STAGE 2 : 14 k16 steps ===================
    #pragma unroll 2
    for (int s = 0; s < 14; ++s) {
        const int j   = s >> 1;
        const int p0  = 8 * (s & 1) + tig;
        const int cb  = mbase + g + j;
        uint32_t ahi[2][4], alo[2][4];
        #pragma unroll
        for (int t = 0; t < 2; ++t) {
            int c0 = cb + 16 * t;
            ahi[t][0] = s_mhi[p0 * 264 + c0];
            ahi[t][1] = s_mhi[p0 * 264 + c0 + 8];
            ahi[t][2] = s_mhi[(p0 + 4) * 264 + c0];
            ahi[t][3] = s_mhi[(p0 + 4) * 264 + c0 + 8];
            alo[t][0] = s_mlo[p0 * 264 + c0];
            alo[t][1] = s_mlo[p0 * 264 + c0 + 8];
            alo[t][2] = s_mlo[(p0 + 4) * 264 + c0];
            alo[t][3] = s_mlo[(p0 + 4) * 264 + c0 + 8];
        }
        const uint2* bfp = (const uint2*)s_bf + s * 128 + lane;
        #pragma unroll
        for (int nt = 0; nt < 4; ++nt) {
            uint2 bv = bfp[nt * 32];
            #pragma unroll
            for (int t = 0; t < 2; ++t) {
                mma16(acc[t][nt], ahi[t][0], ahi[t][1], ahi[t][2], ahi[t][3], bv.x, bv.y);
                mma16(acc[t][nt], alo[t][0], alo[t][1], alo[t][2], alo[t][3], bv.x, bv.y);
            }
        }
    }

    // ---- epilogue 2: acc -> out (+fused bias) ----
    float* ob = out + (size_t)b * CCH * HW + h * WWW;
    #pragma unroll
    for (int t = 0; t < 2; ++t) {
        int r0 = mbase + 16 * t + g;
        #pragma unroll
        for (int nt = 0; nt < 4; ++nt) {
            int n0 = nt * 8 + tig * 2;
            int n1 = n0 + 1;
            if (n0 < CCH) {
                float bq = s_B2[n0];
                ob[(size_t)n0 * HW + r0]     = acc[t][nt][0] + bq;
                ob[(size_t)n0 * HW + r0 + 8] = acc[t][nt][2] + bq;
            }
            if (n1 < CCH) {
                float bq = s_B2[n1];
                ob[(size_t)n1 * HW + r0]     = acc[t][nt][1] + bq;
                ob[(size_t)n1 * HW + r0 + 8] = acc[t][nt][3] + bq;
            }
        }
    }
}

// ---------------------------------------------------------------------------
extern "C" void kernel_launch(void* const* d_in, const int* in_sizes, int n_in,
                              void* d_out, int out_size) {
    const float* x      = (const float*)d_in[0];
    const float* weight = (const float*)d_in[1];
    const float* bias   = (const float*)d_in[2];
    const float* w_t    = (const float*)d_in[3];
    const float* b_t    = (const float*)d_in[4];
    const float* w_m    = (const float*)d_in[5];
    const float* b_m    = (const float*)d_in[6];
    float* out = (float*)d_out;

    cudaFuncSetAttribute(harmonic_mma_kernel,
                         cudaFuncAttributeMaxDynamicSharedMemorySize, SMEM_BYTES);
    harmonic_mma_kernel<<<BBATCH * HHH, 256, SMEM_BYTES>>>(
        x, weight, bias, w_t, b_t, w_m, b_m, out);
}

// round 9
// speedup vs baseline: 2.8390x; 1.4043x over previous
#include <cuda_runtime.h>
#include <cuda_fp16.h>
#include <cstdint>

#define BBATCH 8
#define CCH    28
#define HHH    256
#define WWW    256
#define KHH    7
#define NGI    49
#define HW     (HHH*WWW)
#define PADH   3

// smem u32-index layout
#define BF_OFF    0                    // 14 steps x 2 np x 32 lanes x uint4 = 3584 u32
#define BF_U32    3584
#define MIDH_OFF  (BF_OFF+BF_U32)      // 16 pair-rows x 264 = 4224 (hi plane only)
#define STG_OFF   (MIDH_OFF+4224)      // 8 warps x (hi 320 + lo 320) = 5120
#define TBL_OFF   (STG_OFF+5120)
// tables: cf0[56] cf1[56] cy0[56] cy1[56] cpl[56] cgi[56] b1[32] B2[32] ns1[1]
#define SMEM_U32  (TBL_OFF + 56*6 + 64 + 16)
#define SMEM_BYTES (SMEM_U32*4)

static __device__ __forceinline__ void mma16(float* d,
                                             uint32_t a0, uint32_t a1,
                                             uint32_t a2, uint32_t a3,
                                             uint32_t b0, uint32_t b1) {
    asm volatile(
        "mma.sync.aligned.m16n8k16.row.col.f32.f16.f16.f32 "
        "{%0,%1,%2,%3}, {%4,%5,%6,%7}, {%8,%9}, {%0,%1,%2,%3};"
        : "+f"(d[0]), "+f"(d[1]), "+f"(d[2]), "+f"(d[3])
        : "r"(a0), "r"(a1), "r"(a2), "r"(a3), "r"(b0), "r"(b1));
}
static __device__ __forceinline__ uint32_t h2u(__half2 h) {
    return *reinterpret_cast<uint32_t*>(&h);
}
static __device__ __forceinline__ void packhl(float a, float b,
                                              uint32_t& hi, uint32_t& lo) {
    __half2 h = __floats2half2_rn(a, b);
    float2 hf = __half22float2(h);
    __half2 l = __floats2half2_rn(a - hf.x, b - hf.y);
    hi = h2u(h);
    lo = h2u(l);
}

__global__ void __launch_bounds__(256, 3)
harmonic_mma_kernel(const float* __restrict__ x,
                    const float* __restrict__ weight,
                    const float* __restrict__ bias,
                    const float* __restrict__ w_t,
                    const float* __restrict__ b_t,
                    const float* __restrict__ w_m,
                    const float* __restrict__ b_m,
                    float* __restrict__ out) {
    extern __shared__ uint32_t smu[];
    uint32_t* s_bf  = smu + BF_OFF;
    uint32_t* s_mhi = smu + MIDH_OFF;
    uint32_t* s_stg = smu + STG_OFF;
    float*    s_f0  = (float*)(smu + TBL_OFF);   // compacted
    float*    s_f1  = s_f0 + 56;
    int*      s_y0  = (int*)(s_f1 + 56);
    int*      s_y1  = s_y0 + 56;
    int*      s_pl  = s_y1 + 56;
    int*      s_gi  = s_pl + 56;
    float*    s_b1  = (float*)(s_gi + 56);       // 32
    float*    s_B2  = s_b1 + 32;                 // 32
    int*      s_ns  = (int*)(s_B2 + 32);

    const int tid  = threadIdx.x;
    const int wid  = tid >> 5;
    const int lane = tid & 31;
    const int g    = lane >> 2;
    const int tig  = lane & 3;
    const int h    = blockIdx.x & 255;
    const int b    = blockIdx.x >> 8;
    const int mbase = wid * 32;

    // ---- phase A: raw per-h tables (uncompacted, into upper scratch of s_bf) ----
    float* r_f0 = (float*)s_bf;          // reuse BF region as scratch pre-stage
    float* r_f1 = r_f0 + 49;
    int*   r_y0 = (int*)(r_f1 + 49);
    int*   r_y1 = r_y0 + 49;
    if (tid < NGI) {
        int gg = tid / KHH, ii = tid % KHH;
        float fh = (float)h, fg = (float)gg, fi = (float)ii;
        float t   = __fdiv_rn(fh + 1.0f, fg + 1.0f) * (fi + 1.0f);
        float off = -fi + t - (fh + 1.0f);
        float yp  = fh - (float)PADH + fi + off;
        float y0f = floorf(yp);
        float fy  = yp - y0f;
        int   y0i = (int)y0f;
        float v0 = (y0i >= 0 && y0i <= HHH - 1) ? 1.0f : 0.0f;
        float v1 = (y0i + 1 >= 0 && y0i + 1 <= HHH - 1) ? 1.0f : 0.0f;
        int y0c = y0i < 0 ? 0 : (y0i > HHH - 1 ? HHH - 1 : y0i);
        int y1i = y0i + 1;
        int y1c = y1i < 0 ? 0 : (y1i > HHH - 1 ? HHH - 1 : y1i);
        r_y0[tid] = y0c * WWW;
        r_y1[tid] = y1c * WWW;
        r_f0[tid] = (1.0f - fy) * v0;
        r_f1[tid] = fy * v1;
    }
    if (tid < 32) {
        s_b1[tid] = (tid < CCH) ? bias[tid] : 0.0f;
        float s = 0.0f;
        if (tid < CCH) {
            int f = tid >> 2, cq = tid & 3;
            s = b_m[f];
            #pragma unroll
            for (int g7 = 0; g7 < 7; ++g7) s += w_m[f * 7 + g7] * b_t[g7 * 4 + cq];
        }
        s_B2[tid] = s;
    }
    if (tid < 128) {        // mid halo zeros (hi plane): 16 rows x 8 cols
        int p = tid >> 3, c8 = tid & 7;
        int col = (c8 < 3) ? c8 : 256 + c8;
        s_mhi[p * 264 + col] = 0u;
    }
    __syncthreads();

    // ---- phase B: compact live taps (thread 0; uniform result) ----
    if (tid == 0) {
        int nl = 0;
        for (int gi = 0; gi < NGI; ++gi) {
            float f0 = r_f0[gi], f1 = r_f1[gi];
            if (f0 != 0.0f || f1 != 0.0f) {
                s_f0[nl] = f0; s_f1[nl] = f1;
                s_y0[nl] = r_y0[gi]; s_y1[nl] = r_y1[gi];
                s_pl[nl] = (gi / KHH) * 4;
                s_gi[nl] = gi;
                ++nl;
            }
        }
        int ns1 = (nl + 3) >> 2;
        for (int p = nl; p < ns1 * 4; ++p) {
            s_f0[p] = 0.0f; s_f1[p] = 0.0f;
            s_y0[p] = 0;    s_y1[p] = 0;
            s_pl[p] = 0;    s_gi[p] = -1;
        }
        *s_ns = ns1;
    }
    __syncthreads();
    const int ns1 = *s_ns;

    // ---- B1 fragments over compacted slots: [s][np][lane] uint4 ----
    for (int idx = tid; idx < ns1 * 64; idx += 256) {
        int s  = idx >> 6;
        int np = (idx >> 5) & 1;
        int ln = idx & 31;
        int na = (2 * np) * 8 + (ln >> 2);
        int nb = na + 8;
        int tt = ln & 3;
        int k0 = 16 * s + 2 * tt;
        float w4[4];
        #pragma unroll
        for (int e = 0; e < 4; ++e) {
            int n = (e >> 1) ? nb : na;
            int kb = k0 + 8 * ((e >> 1) ? 0 : 0); // placeholder
            (void)kb;
            w4[e] = 0.0f;
            (void)n;
        }
        // elements: x=(na, k0,k0+1) y=(na, k0+8,k0+9) z=(nb, k0,k0+1) w=(nb, k0+8,k0+9)
        uint32_t u[4];
        #pragma unroll
        for (int e = 0; e < 4; ++e) {
            int n  = (e >> 1) ? nb : na;
            int kk = k0 + 8 * (e & 1);
            float va = 0.0f, vb = 0.0f;
            if (n < CCH) {
                int sl0 = kk >> 2, c0 = kk & 3;
                int sl1 = (kk + 1) >> 2, c1 = (kk + 1) & 3;
                int gia = (sl0 < ns1 * 4) ? s_gi[sl0] : -1;
                int gib = (sl1 < ns1 * 4) ? s_gi[sl1] : -1;
                if (gia >= 0)
                    va = weight[(n * CCH + (gia / KHH) * 4 + c0) * KHH + (gia % KHH)];
                if (gib >= 0)
                    vb = weight[(n * CCH + (gib / KHH) * 4 + c1) * KHH + (gib % KHH)];
            }
            u[e] = h2u(__floats2half2_rn(va, vb));
        }
        ((uint4*)s_bf)[idx] = make_uint4(u[0], u[1], u[2], u[3]);
    }
    __syncthreads();

    const float* xb = x + (size_t)b * CCH * HW;
    uint32_t* stgh = s_stg + wid * 640;
    uint32_t* stgl = stgh + 320;

    float acc[2][4][4];
    #pragma unroll
    for (int t = 0; t < 2; ++t)
        #pragma unroll
        for (int nt = 0; nt < 4; ++nt)
            #pragma unroll
            for (int r = 0; r < 4; ++r) acc[t][nt][r] = 0.0f;

    // =================== STAGE 1 : ns1 k16 steps (compacted) ===================
    for (int s = 0; s < ns1; ++s) {
        #pragma unroll
        for (int r = 0; r < 2; ++r) {
            float vv[8];
            #pragma unroll
            for (int tp = 0; tp < 2; ++tp) {
                const int sl = 4 * s + 2 * r + tp;
                const int o0 = s_y0[sl], o1 = s_y1[sl];
                const float f0 = s_f0[sl], f1 = s_f1[sl];
                const float* pp = xb + (size_t)s_pl[sl] * HW + mbase + lane;
                #pragma unroll
                for (int c = 0; c < 4; ++c) {
                    float a0 = __ldg(pp + c * HW + o0);
                    float a1 = __ldg(pp + c * HW + o1);
                    vv[tp * 4 + c] = a0 * f0 + a1 * f1;
                }
            }
            #pragma unroll
            for (int tp = 0; tp < 2; ++tp) {
                uint32_t h01, l01, h23, l23;
                packhl(vv[4 * tp + 0], vv[4 * tp + 1], h01, l01);
                packhl(vv[4 * tp + 2], vv[4 * tp + 3], h23, l23);
                int kp = 4 * r + 2 * tp;
                stgh[kp * 40 + lane]       = h01;
                stgh[(kp + 1) * 40 + lane] = h23;
                stgl[kp * 40 + lane]       = l01;
                stgl[(kp + 1) * 40 + lane] = l23;
            }
        }
        __syncwarp();

        uint32_t ahi[2][4], alo[2][4];
        #pragma unroll
        for (int t = 0; t < 2; ++t) {
            int mb2 = 16 * t + g;
            ahi[t][0] = stgh[tig * 40 + mb2];
            ahi[t][1] = stgh[tig * 40 + mb2 + 8];
            ahi[t][2] = stgh[(tig + 4) * 40 + mb2];
            ahi[t][3] = stgh[(tig + 4) * 40 + mb2 + 8];
            alo[t][0] = stgl[tig * 40 + mb2];
            alo[t][1] = stgl[tig * 40 + mb2 + 8];
            alo[t][2] = stgl[(tig + 4) * 40 + mb2];
            alo[t][3] = stgl[(tig + 4) * 40 + mb2 + 8];
        }
        __syncwarp();

        const uint4* bfp = (const uint4*)s_bf + s * 64 + lane;
        #pragma unroll
        for (int np = 0; np < 2; ++np) {
            uint4 bv = bfp[np * 32];
            #pragma unroll
            for (int t = 0; t < 2; ++t) {
                mma16(acc[t][2*np],   ahi[t][0], ahi[t][1], ahi[t][2], ahi[t][3], bv.x, bv.y);
                mma16(acc[t][2*np],   alo[t][0], alo[t][1], alo[t][2], alo[t][3], bv.x, bv.y);
                mma16(acc[t][2*np+1], ahi[t][0], ahi[t][1], ahi[t][2], ahi[t][3], bv.z, bv.w);
                mma16(acc[t][2*np+1], alo[t][0], alo[t][1], alo[t][2], alo[t][3], bv.z, bv.w);
            }
        }
    }

    // ---- epilogue 1: acc -> mid hi plane (+bias) ----
    #pragma unroll
    for (int t = 0; t < 2; ++t) {
        #pragma unroll
        for (int nt = 0; nt < 2; ++nt) {
            #pragma unroll
            for (int r = 0; r < 4; ++r) {
                int n   = nt * 8 + 2 * tig + (r & 1);
                int row = mbase + 16 * t + g + 8 * (r >> 1);
                float va = acc[t][nt][r]     + s_b1[n];
                float vb = acc[t][nt + 2][r] + s_b1[n + 16];
                s_mhi[n * 264 + 3 + row] = h2u(__floats2half2_rn(va, vb));
            }
        }
    }
    __syncthreads();

    // ---- B2 fragments: k = j*32 + kk, i = (kk>>1) + 16*(kk&1) ; uint4 ----
    for (int idx = tid; idx < 896; idx += 256) {
        int s  = idx >> 6;
        int np = (idx >> 5) & 1;
        int ln = idx & 31;
        int na = (2 * np) * 8 + (ln >> 2);
        int nb = na + 8;
        int tt = ln & 3;
        int j  = s >> 1;
        int ie = 8 * (s & 1) + tt;
        uint32_t u[4];
        #pragma unroll
        for (int e = 0; e < 4; ++e) {
            int n  = (e >> 1) ? nb : na;
            int i0 = ie + 4 * (e & 1);       // k-even of the pair
            float va = 0.0f, vb = 0.0f;
            if (n < CCH) {
                int f = n >> 2, cq = n & 3;
                #pragma unroll
                for (int g7 = 0; g7 < 7; ++g7) {
                    float wm = w_m[f * 7 + g7];
                    int base = (g7 * 4 + cq) * CCH;
                    if (i0 < CCH)      va += wm * w_t[(base + i0) * KHH + j];
                    if (i0 + 16 < CCH) vb += wm * w_t[(base + i0 + 16) * KHH + j];
                }
            }
            u[e] = h2u(__floats2half2_rn(va, vb));
        }
        ((uint4*)s_bf)[idx] = make_uint4(u[0], u[1], u[2], u[3]);
    }
    #pragma unroll
    for (int t = 0; t < 2; ++t)
        #pragma unroll
        for (int nt = 0; nt < 4; ++nt)
            #pragma unroll
            for (int r = 0; r < 4; ++r) acc[t][nt][r] = 0.0f;
    __syncthreads();

    // =================== STAGE 2 : 14 k16 steps, single-A-term ===================
    #pragma unroll 2
    for (int s = 0; s < 14; ++s) {
        const int j  = s >> 1;
        const int p0 = 8 * (s & 1) + tig;
        const int cb = mbase + g + j;
        uint32_t ahi[2][4];
        #pragma unroll
        for (int t = 0; t < 2; ++t) {
            int c0 = cb + 16 * t;
            ahi[t][0] = s_mhi[p0 * 264 + c0];
            ahi[t][1] = s_mhi[p0 * 264 + c0 + 8];
            ahi[t][2] = s_mhi[(p0 + 4) * 264 + c0];
            ahi[t][3] = s_mhi[(p0 + 4) * 264 + c0 + 8];
        }
        const uint4* bfp = (const uint4*)s_bf + s * 64 + lane;
        #pragma unroll
        for (int np = 0; np < 2; ++np) {
            uint4 bv = bfp[np * 32];
            #pragma unroll
            for (int t = 0; t < 2; ++t) {
                mma16(acc[t][2*np],   ahi[t][0], ahi[t][1], ahi[t][2], ahi[t][3], bv.x, bv.y);
                mma16(acc[t][2*np+1], ahi[t][0], ahi[t][1], ahi[t][2], ahi[t][3], bv.z, bv.w);
            }
        }
    }

    // ---- epilogue 2: acc -> out (+fused bias) ----
    // stage-2 k-mapping pairs (i, i+16) in half lanes; D rows/cols unchanged.
    float* ob = out + (size_t)b * CCH * HW + h * WWW;
    #pragma unroll
    for (int t = 0; t < 2; ++t) {
        int r0 = mbase + 16 * t + g;
        #pragma unroll
        for (int nt = 0; nt < 4; ++nt) {
            int n0 = nt * 8 + tig * 2;
            int n1 = n0 + 1;
            if (n0 < CCH) {
                float bq = s_B2[n0];
                ob[(size_t)n0 * HW + r0]     = acc[t][nt][0] + bq;
                ob[(size_t)n0 * HW + r0 + 8] = acc[t][nt][2] + bq;
            }
            if (n1 < CCH) {
                float bq = s_B2[n1];
                ob[(size_t)n1 * HW + r0]     = acc[t][nt][1] + bq;
                ob[(size_t)n1 * HW + r0 + 8] = acc[t][nt][3] + bq;
            }
        }
    }
}

// ---------------------------------------------------------------------------
extern "C" void kernel_launch(void* const* d_in, const int* in_sizes, int n_in,
                              void* d_out, int out_size) {
    const float* x      = (const float*)d_in[0];
    const float* weight = (const float*)d_in[1];
    const float* bias   = (const float*)d_in[2];
    const float* w_t    = (const float*)d_in[3];
    const float* b_t    = (const float*)d_in[4];
    const float* w_m    = (const float*)d_in[5];
    const float* b_m    = (const float*)d_in[6];
    float* out = (float*)d_out;

    cudaFuncSetAttribute(harmonic_mma_kernel,
                         cudaFuncAttributeMaxDynamicSharedMemorySize, SMEM_BYTES);
    harmonic_mma_kernel<<<BBATCH * HHH, 256, SMEM_BYTES>>>(
        x, weight, bias, w_t, b_t, w_m, b_m, out);
}

// round 10
// speedup vs baseline: 3.1484x; 1.1090x over previous
#include <cuda_runtime.h>
#include <cuda_fp16.h>
#include <cstdint>

#define BBATCH 8
#define CCH    28
#define HHH    256
#define WWW    256
#define KHH    7
#define NGI    49
#define HW     (HHH*WWW)
#define PADH   3

// smem u32-index layout
#define BF_OFF    0                    // 14 steps x 2 np x 32 lanes x uint4 = 3584 u32
#define BF_U32    3584
#define MIDH_OFF  (BF_OFF+BF_U32)      // 16 pair-rows x 264 = 4224 (fp16x2 plane)
#define STG_OFF   (MIDH_OFF+4224)      // 8 warps x 320 (hi only)
#define TBL_OFF   (STG_OFF+2560)
// tables: cf0[56] cf1[56] cy0[56] cy1[56] cpl[56] cgi[56] b1[32] B2[32] ns1[..]
#define SMEM_U32  (TBL_OFF + 56*6 + 64 + 16)
#define SMEM_BYTES (SMEM_U32*4)

static __device__ __forceinline__ void mma16(float* d,
                                             uint32_t a0, uint32_t a1,
                                             uint32_t a2, uint32_t a3,
                                             uint32_t b0, uint32_t b1) {
    asm volatile(
        "mma.sync.aligned.m16n8k16.row.col.f32.f16.f16.f32 "
        "{%0,%1,%2,%3}, {%4,%5,%6,%7}, {%8,%9}, {%0,%1,%2,%3};"
        : "+f"(d[0]), "+f"(d[1]), "+f"(d[2]), "+f"(d[3])
        : "r"(a0), "r"(a1), "r"(a2), "r"(a3), "r"(b0), "r"(b1));
}
static __device__ __forceinline__ uint32_t h2u(__half2 h) {
    return *reinterpret_cast<uint32_t*>(&h);
}

__global__ void __launch_bounds__(256, 3)
harmonic_mma_kernel(const float* __restrict__ x,
                    const float* __restrict__ weight,
                    const float* __restrict__ bias,
                    const float* __restrict__ w_t,
                    const float* __restrict__ b_t,
                    const float* __restrict__ w_m,
                    const float* __restrict__ b_m,
                    float* __restrict__ out) {
    extern __shared__ uint32_t smu[];
    uint32_t* s_bf  = smu + BF_OFF;
    uint32_t* s_mhi = smu + MIDH_OFF;
    uint32_t* s_stg = smu + STG_OFF;
    float*    s_f0  = (float*)(smu + TBL_OFF);   // compacted tap tables
    float*    s_f1  = s_f0 + 56;
    int*      s_y0  = (int*)(s_f1 + 56);
    int*      s_y1  = s_y0 + 56;
    int*      s_pl  = s_y1 + 56;
    int*      s_gi  = s_pl + 56;
    float*    s_b1  = (float*)(s_gi + 56);       // 32
    float*    s_B2  = s_b1 + 32;                 // 32
    int*      s_ns  = (int*)(s_B2 + 32);

    const int tid  = threadIdx.x;
    const int wid  = tid >> 5;
    const int lane = tid & 31;
    const int g    = lane >> 2;
    const int tig  = lane & 3;
    const int h    = blockIdx.x & 255;
    const int b    = blockIdx.x >> 8;
    const int mbase = wid * 32;

    // ---- phase A: raw per-h tables (scratch in BF region) ----
    float* r_f0 = (float*)s_bf;
    float* r_f1 = r_f0 + 49;
    int*   r_y0 = (int*)(r_f1 + 49);
    int*   r_y1 = r_y0 + 49;
    if (tid < NGI) {
        int gg = tid / KHH, ii = tid % KHH;
        float fh = (float)h, fg = (float)gg, fi = (float)ii;
        float t   = __fdiv_rn(fh + 1.0f, fg + 1.0f) * (fi + 1.0f);
        float off = -fi + t - (fh + 1.0f);
        float yp  = fh - (float)PADH + fi + off;
        float y0f = floorf(yp);
        float fy  = yp - y0f;
        int   y0i = (int)y0f;
        float v0 = (y0i >= 0 && y0i <= HHH - 1) ? 1.0f : 0.0f;
        float v1 = (y0i + 1 >= 0 && y0i + 1 <= HHH - 1) ? 1.0f : 0.0f;
        int y0c = y0i < 0 ? 0 : (y0i > HHH - 1 ? HHH - 1 : y0i);
        int y1i = y0i + 1;
        int y1c = y1i < 0 ? 0 : (y1i > HHH - 1 ? HHH - 1 : y1i);
        r_y0[tid] = y0c * WWW;
        r_y1[tid] = y1c * WWW;
        r_f0[tid] = (1.0f - fy) * v0;
        r_f1[tid] = fy * v1;
    }
    if (tid < 32) {
        s_b1[tid] = (tid < CCH) ? bias[tid] : 0.0f;
        float s = 0.0f;
        if (tid < CCH) {
            int f = tid >> 2, cq = tid & 3;
            s = b_m[f];
            #pragma unroll
            for (int g7 = 0; g7 < 7; ++g7) s += w_m[f * 7 + g7] * b_t[g7 * 4 + cq];
        }
        s_B2[tid] = s;
    }
    if (tid < 128) {        // mid halo zeros: 16 pair-rows x 8 cols
        int p = tid >> 3, c8 = tid & 7;
        int col = (c8 < 3) ? c8 : 256 + c8;
        s_mhi[p * 264 + col] = 0u;
    }
    __syncthreads();

    // ---- phase B: compact live taps (thread 0; uniform) ----
    if (tid == 0) {
        int nl = 0;
        for (int gi = 0; gi < NGI; ++gi) {
            float f0 = r_f0[gi], f1 = r_f1[gi];
            if (f0 != 0.0f || f1 != 0.0f) {
                s_f0[nl] = f0; s_f1[nl] = f1;
                s_y0[nl] = r_y0[gi]; s_y1[nl] = r_y1[gi];
                s_pl[nl] = (gi / KHH) * 4;
                s_gi[nl] = gi;
                ++nl;
            }
        }
        int ns1 = (nl + 3) >> 2;
        for (int p = nl; p < ns1 * 4; ++p) {
            s_f0[p] = 0.0f; s_f1[p] = 0.0f;
            s_y0[p] = 0;    s_y1[p] = 0;
            s_pl[p] = 0;    s_gi[p] = -1;
        }
        *s_ns = ns1;
    }
    __syncthreads();
    const int ns1 = *s_ns;

    // ---- B1 fragments (compacted): [s][np][lane] uint4 ----
    for (int idx = tid; idx < ns1 * 64; idx += 256) {
        int s  = idx >> 6;
        int np = (idx >> 5) & 1;
        int ln = idx & 31;
        int na = (2 * np) * 8 + (ln >> 2);
        int nb = na + 8;
        int tt = ln & 3;
        int k0 = 16 * s + 2 * tt;
        uint32_t u[4];
        #pragma unroll
        for (int e = 0; e < 4; ++e) {
            int n  = (e >> 1) ? nb : na;
            int kk = k0 + 8 * (e & 1);
            float va = 0.0f, vb = 0.0f;
            if (n < CCH) {
                int sl0 = kk >> 2, c0 = kk & 3;
                int sl1 = (kk + 1) >> 2, c1 = (kk + 1) & 3;
                int gia = (sl0 < ns1 * 4) ? s_gi[sl0] : -1;
                int gib = (sl1 < ns1 * 4) ? s_gi[sl1] : -1;
                if (gia >= 0)
                    va = weight[(n * CCH + (gia / KHH) * 4 + c0) * KHH + (gia % KHH)];
                if (gib >= 0)
                    vb = weight[(n * CCH + (gib / KHH) * 4 + c1) * KHH + (gib % KHH)];
            }
            u[e] = h2u(__floats2half2_rn(va, vb));
        }
        ((uint4*)s_bf)[idx] = make_uint4(u[0], u[1], u[2], u[3]);
    }
    __syncthreads();

    const float* xb = x + (size_t)b * CCH * HW;
    uint32_t* stgh = s_stg + wid * 320;

    float acc[2][4][4];
    #pragma unroll
    for (int t = 0; t < 2; ++t)
        #pragma unroll
        for (int nt = 0; nt < 4; ++nt)
            #pragma unroll
            for (int r = 0; r < 4; ++r) acc[t][nt][r] = 0.0f;

    // =================== STAGE 1 : ns1 k16 steps, single-A-term ===============
    for (int s = 0; s < ns1; ++s) {
        #pragma unroll
        for (int r = 0; r < 2; ++r) {
            float vv[8];
            #pragma unroll
            for (int tp = 0; tp < 2; ++tp) {
                const int sl = 4 * s + 2 * r + tp;
                const int o0 = s_y0[sl], o1 = s_y1[sl];
                const float f0 = s_f0[sl], f1 = s_f1[sl];
                const float* pp = xb + (size_t)s_pl[sl] * HW + mbase + lane;
                #pragma unroll
                for (int c = 0; c < 4; ++c) {
                    float a0 = __ldg(pp + c * HW + o0);
                    float a1 = __ldg(pp + c * HW + o1);
                    vv[tp * 4 + c] = a0 * f0 + a1 * f1;
                }
            }
            #pragma unroll
            for (int tp = 0; tp < 2; ++tp) {
                int kp = 4 * r + 2 * tp;
                stgh[kp * 40 + lane]       = h2u(__floats2half2_rn(vv[4*tp+0], vv[4*tp+1]));
                stgh[(kp + 1) * 40 + lane] = h2u(__floats2half2_rn(vv[4*tp+2], vv[4*tp+3]));
            }
        }
        __syncwarp();

        uint32_t ahi[2][4];
        #pragma unroll
        for (int t = 0; t < 2; ++t) {
            int mb2 = 16 * t + g;
            ahi[t][0] = stgh[tig * 40 + mb2];
            ahi[t][1] = stgh[tig * 40 + mb2 + 8];
            ahi[t][2] = stgh[(tig + 4) * 40 + mb2];
            ahi[t][3] = stgh[(tig + 4) * 40 + mb2 + 8];
        }
        __syncwarp();

        const uint4* bfp = (const uint4*)s_bf + s * 64 + lane;
        #pragma unroll
        for (int np = 0; np < 2; ++np) {
            uint4 bv = bfp[np * 32];
            #pragma unroll
            for (int t = 0; t < 2; ++t) {
                mma16(acc[t][2*np],   ahi[t][0], ahi[t][1], ahi[t][2], ahi[t][3], bv.x, bv.y);
                mma16(acc[t][2*np+1], ahi[t][0], ahi[t][1], ahi[t][2], ahi[t][3], bv.z, bv.w);
            }
        }
    }

    // ---- epilogue 1: acc -> mid fp16x2 plane (+bias) ----
    #pragma unroll
    for (int t = 0; t < 2; ++t) {
        #pragma unroll
        for (int nt = 0; nt < 2; ++nt) {
            #pragma unroll
            for (int r = 0; r < 4; ++r) {
                int n   = nt * 8 + 2 * tig + (r & 1);
                int row = mbase + 16 * t + g + 8 * (r >> 1);
                float va = acc[t][nt][r]     + s_b1[n];
                float vb = acc[t][nt + 2][r] + s_b1[n + 16];
                s_mhi[n * 264 + 3 + row] = h2u(__floats2half2_rn(va, vb));
            }
        }
    }
    __syncthreads();

    // ---- B2 fragments: k = j*32 + kk, i = (kk>>1) + 16*(kk&1) ; uint4 ----
    for (int idx = tid; idx < 896; idx += 256) {
        int s  = idx >> 6;
        int np = (idx >> 5) & 1;
        int ln = idx & 31;
        int na = (2 * np) * 8 + (ln >> 2);
        int nb = na + 8;
        int tt = ln & 3;
        int j  = s >> 1;
        int ie = 8 * (s & 1) + tt;
        uint32_t u[4];
        #pragma unroll
        for (int e = 0; e < 4; ++e) {
            int n  = (e >> 1) ? nb : na;
            int i0 = ie + 4 * (e & 1);
            float va = 0.0f, vb = 0.0f;
            if (n < CCH) {
                int f = n >> 2, cq = n & 3;
                #pragma unroll
                for (int g7 = 0; g7 < 7; ++g7) {
                    float wm = w_m[f * 7 + g7];
                    int base = (g7 * 4 + cq) * CCH;
                    if (i0 < CCH)      va += wm * w_t[(base + i0) * KHH + j];
                    if (i0 + 16 < CCH) vb += wm * w_t[(base + i0 + 16) * KHH + j];
                }
            }
            u[e] = h2u(__floats2half2_rn(va, vb));
        }
        ((uint4*)s_bf)[idx] = make_uint4(u[0], u[1], u[2], u[3]);
    }
    #pragma unroll
    for (int t = 0; t < 2; ++t)
        #pragma unroll
        for (int nt = 0; nt < 4; ++nt)
            #pragma unroll
            for (int r = 0; r < 4; ++r) acc[t][nt][r] = 0.0f;
    __syncthreads();

    // =================== STAGE 2 : 14 k16 steps, single-A-term ================
    #pragma unroll 2
    for (int s = 0; s < 14; ++s) {
        const int j  = s >> 1;
        const int p0 = 8 * (s & 1) + tig;
        const int cb = mbase + g + j;
        uint32_t ahi[2][4];
        #pragma unroll
        for (int t = 0; t < 2; ++t) {
            int c0 = cb + 16 * t;
            ahi[t][0] = s_mhi[p0 * 264 + c0];
            ahi[t][1] = s_mhi[p0 * 264 + c0 + 8];
            ahi[t][2] = s_mhi[(p0 + 4) * 264 + c0];
            ahi[t][3] = s_mhi[(p0 + 4) * 264 + c0 + 8];
        }
        const uint4* bfp = (const uint4*)s_bf + s * 64 + lane;
        #pragma unroll
        for (int np = 0; np < 2; ++np) {
            uint4 bv = bfp[np * 32];
            #pragma unroll
            for (int t = 0; t < 2; ++t) {
                mma16(acc[t][2*np],   ahi[t][0], ahi[t][1], ahi[t][2], ahi[t][3], bv.x, bv.y);
                mma16(acc[t][2*np+1], ahi[t][0], ahi[t][1], ahi[t][2], ahi[t][3], bv.z, bv.w);
            }
        }
    }

    // ---- epilogue 2: acc -> out (+fused bias) ----
    float* ob = out + (size_t)b * CCH * HW + h * WWW;
    #pragma unroll
    for (int t = 0; t < 2; ++t) {
        int r0 = mbase + 16 * t + g;
        #pragma unroll
        for (int nt = 0; nt < 4; ++nt) {
            int n0 = nt * 8 + tig * 2;
            int n1 = n0 + 1;
            if (n0 < CCH) {
                float bq = s_B2[n0];
                ob[(size_t)n0 * HW + r0]     = acc[t][nt][0] + bq;
                ob[(size_t)n0 * HW + r0 + 8] = acc[t][nt][2] + bq;
            }
            if (n1 < CCH) {
                float bq = s_B2[n1];
                ob[(size_t)n1 * HW + r0]     = acc[t][nt][1] + bq;
                ob[(size_t)n1 * HW + r0 + 8] = acc[t][nt][3] + bq;
            }
        }
    }
}

// ---------------------------------------------------------------------------
extern "C" void kernel_launch(void* const* d_in, const int* in_sizes, int n_in,
                              void* d_out, int out_size) {
    const float* x      = (const float*)d_in[0];
    const float* weight = (const float*)d_in[1];
    const float* bias   = (const float*)d_in[2];
    const float* w_t    = (const float*)d_in[3];
    const float* b_t    = (const float*)d_in[4];
    const float* w_m    = (const float*)d_in[5];
    const float* b_m    = (const float*)d_in[6];
    float* out = (float*)d_out;

    cudaFuncSetAttribute(harmonic_mma_kernel,
                         cudaFuncAttributeMaxDynamicSharedMemorySize, SMEM_BYTES);
    harmonic_mma_kernel<<<BBATCH * HHH, 256, SMEM_BYTES>>>(
        x, weight, bias, w_t, b_t, w_m, b_m, out);
}

// round 11
// speedup vs baseline: 3.1974x; 1.0156x over previous
#include <cuda_runtime.h>
#include <cuda_fp16.h>
#include <cstdint>

#define BBATCH 8
#define CCH    28
#define HHH    256
#define WWW    256
#define KHH    7
#define NGI    49
#define HW     (HHH*WWW)
#define PADH   3

// smem u32-index layout
#define BF_OFF    0                    // 14 steps x 2 np x 32 lanes x uint4 = 3584 u32
#define BF_U32    3584
#define MIDH_OFF  (BF_OFF+BF_U32)      // 16 pair-rows x 264 = 4224 (fp16x2 plane)
#define STG_OFF   (MIDH_OFF+4224)      // 8 warps x 320
#define TBL_OFF   (STG_OFF+2560)
#define SMEM_U32  (TBL_OFF + 56*6 + 64 + 16)
#define SMEM_BYTES (SMEM_U32*4)

static __device__ __forceinline__ void mma16(float* d,
                                             uint32_t a0, uint32_t a1,
                                             uint32_t a2, uint32_t a3,
                                             uint32_t b0, uint32_t b1) {
    asm volatile(
        "mma.sync.aligned.m16n8k16.row.col.f32.f16.f16.f32 "
        "{%0,%1,%2,%3}, {%4,%5,%6,%7}, {%8,%9}, {%0,%1,%2,%3};"
        : "+f"(d[0]), "+f"(d[1]), "+f"(d[2]), "+f"(d[3])
        : "r"(a0), "r"(a1), "r"(a2), "r"(a3), "r"(b0), "r"(b1));
}
static __device__ __forceinline__ uint32_t h2u(__half2 h) {
    return *reinterpret_cast<uint32_t*>(&h);
}

__global__ void __launch_bounds__(256, 3)
harmonic_mma_kernel(const float* __restrict__ x,
                    const float* __restrict__ weight,
                    const float* __restrict__ bias,
                    const float* __restrict__ w_t,
                    const float* __restrict__ b_t,
                    const float* __restrict__ w_m,
                    const float* __restrict__ b_m,
                    float* __restrict__ out) {
    extern __shared__ uint32_t smu[];
    uint32_t* s_bf  = smu + BF_OFF;
    uint32_t* s_mhi = smu + MIDH_OFF;
    uint32_t* s_stg = smu + STG_OFF;
    float*    s_f0  = (float*)(smu + TBL_OFF);
    float*    s_f1  = s_f0 + 56;
    int*      s_y0  = (int*)(s_f1 + 56);
    int*      s_y1  = s_y0 + 56;
    int*      s_pl  = s_y1 + 56;
    int*      s_gi  = s_pl + 56;
    float*    s_b1  = (float*)(s_gi + 56);
    float*    s_B2  = s_b1 + 32;
    int*      s_ns  = (int*)(s_B2 + 32);

    const int tid  = threadIdx.x;
    const int wid  = tid >> 5;
    const int lane = tid & 31;
    const int g    = lane >> 2;
    const int tig  = lane & 3;
    const int h    = blockIdx.x & 255;
    const int b    = blockIdx.x >> 8;
    const int mbase = wid * 32;

    // ---- phase A: raw per-h tables (scratch in BF region) ----
    float* r_f0 = (float*)s_bf;
    float* r_f1 = r_f0 + 49;
    int*   r_y0 = (int*)(r_f1 + 49);
    int*   r_y1 = r_y0 + 49;
    if (tid < NGI) {
        int gg = tid / KHH, ii = tid % KHH;
        float fh = (float)h, fg = (float)gg, fi = (float)ii;
        float t   = __fdiv_rn(fh + 1.0f, fg + 1.0f) * (fi + 1.0f);
        float off = -fi + t - (fh + 1.0f);
        float yp  = fh - (float)PADH + fi + off;
        float y0f = floorf(yp);
        float fy  = yp - y0f;
        int   y0i = (int)y0f;
        float v0 = (y0i >= 0 && y0i <= HHH - 1) ? 1.0f : 0.0f;
        float v1 = (y0i + 1 >= 0 && y0i + 1 <= HHH - 1) ? 1.0f : 0.0f;
        int y0c = y0i < 0 ? 0 : (y0i > HHH - 1 ? HHH - 1 : y0i);
        int y1i = y0i + 1;
        int y1c = y1i < 0 ? 0 : (y1i > HHH - 1 ? HHH - 1 : y1i);
        r_y0[tid] = y0c * WWW;
        r_y1[tid] = y1c * WWW;
        r_f0[tid] = (1.0f - fy) * v0;
        r_f1[tid] = fy * v1;
    }
    if (tid < 32) {
        s_b1[tid] = (tid < CCH) ? bias[tid] : 0.0f;
        float s = 0.0f;
        if (tid < CCH) {
            int f = tid >> 2, cq = tid & 3;
            s = b_m[f];
            #pragma unroll
            for (int g7 = 0; g7 < 7; ++g7) s += w_m[f * 7 + g7] * b_t[g7 * 4 + cq];
        }
        s_B2[tid] = s;
    }
    if (tid < 128) {
        int p = tid >> 3, c8 = tid & 7;
        int col = (c8 < 3) ? c8 : 256 + c8;
        s_mhi[p * 264 + col] = 0u;
    }
    __syncthreads();

    // ---- phase B: compact live taps ----
    if (tid == 0) {
        int nl = 0;
        for (int gi = 0; gi < NGI; ++gi) {
            float f0 = r_f0[gi], f1 = r_f1[gi];
            if (f0 != 0.0f || f1 != 0.0f) {
                s_f0[nl] = f0; s_f1[nl] = f1;
                s_y0[nl] = r_y0[gi]; s_y1[nl] = r_y1[gi];
                s_pl[nl] = (gi / KHH) * 4;
                s_gi[nl] = gi;
                ++nl;
            }
        }
        int ns1 = (nl + 3) >> 2;
        for (int p = nl; p < ns1 * 4; ++p) {
            s_f0[p] = 0.0f; s_f1[p] = 0.0f;
            s_y0[p] = 0;    s_y1[p] = 0;
            s_pl[p] = 0;    s_gi[p] = -1;
        }
        *s_ns = ns1;
    }
    __syncthreads();
    const int ns1 = *s_ns;

    // ---- B1 fragments (compacted): [s][np][lane] uint4 ----
    for (int idx = tid; idx < ns1 * 64; idx += 256) {
        int s  = idx >> 6;
        int np = (idx >> 5) & 1;
        int ln = idx & 31;
        int na = (2 * np) * 8 + (ln >> 2);
        int nb = na + 8;
        int tt = ln & 3;
        int k0 = 16 * s + 2 * tt;
        uint32_t u[4];
        #pragma unroll
        for (int e = 0; e < 4; ++e) {
            int n  = (e >> 1) ? nb : na;
            int kk = k0 + 8 * (e & 1);
            float va = 0.0f, vb = 0.0f;
            if (n < CCH) {
                int sl0 = kk >> 2, c0 = kk & 3;
                int sl1 = (kk + 1) >> 2, c1 = (kk + 1) & 3;
                int gia = (sl0 < ns1 * 4) ? s_gi[sl0] : -1;
                int gib = (sl1 < ns1 * 4) ? s_gi[sl1] : -1;
                if (gia >= 0)
                    va = weight[(n * CCH + (gia / KHH) * 4 + c0) * KHH + (gia % KHH)];
                if (gib >= 0)
                    vb = weight[(n * CCH + (gib / KHH) * 4 + c1) * KHH + (gib % KHH)];
            }
            u[e] = h2u(__floats2half2_rn(va, vb));
        }
        ((uint4*)s_bf)[idx] = make_uint4(u[0], u[1], u[2], u[3]);
    }
    __syncthreads();

    const float* xb = x + (size_t)b * CCH * HW;
    uint32_t* stgh = s_stg + wid * 320;

    float acc[2][4][4];
    #pragma unroll
    for (int t = 0; t < 2; ++t)
        #pragma unroll
        for (int nt = 0; nt < 4; ++nt)
            #pragma unroll
            for (int r = 0; r < 4; ++r) acc[t][nt][r] = 0.0f;

    // ======= STAGE 1 : ns1 k16 steps, single-A-term, SW-pipelined gather ======
    float vv[16];
    // prologue: gather step 0
    #pragma unroll
    for (int u = 0; u < 4; ++u) {
        const int sl = u;
        const int o0 = s_y0[sl], o1 = s_y1[sl];
        const float f0 = s_f0[sl], f1 = s_f1[sl];
        const float* pp = xb + (size_t)s_pl[sl] * HW + mbase + lane;
        #pragma unroll
        for (int c = 0; c < 4; ++c) {
            float a0 = __ldg(pp + c * HW + o0);
            float a1 = __ldg(pp + c * HW + o1);
            vv[u * 4 + c] = a0 * f0 + a1 * f1;
        }
    }

    #pragma unroll 1
    for (int s = 0; s < ns1; ++s) {
        // pack + STS current step
        #pragma unroll
        for (int u = 0; u < 4; ++u) {
            stgh[(2 * u) * 40 + lane]     = h2u(__floats2half2_rn(vv[4*u+0], vv[4*u+1]));
            stgh[(2 * u + 1) * 40 + lane] = h2u(__floats2half2_rn(vv[4*u+2], vv[4*u+3]));
        }
        __syncwarp();

        uint32_t ahi[2][4];
        #pragma unroll
        for (int t = 0; t < 2; ++t) {
            int mb2 = 16 * t + g;
            ahi[t][0] = stgh[tig * 40 + mb2];
            ahi[t][1] = stgh[tig * 40 + mb2 + 8];
            ahi[t][2] = stgh[(tig + 4) * 40 + mb2];
            ahi[t][3] = stgh[(tig + 4) * 40 + mb2 + 8];
        }
        __syncwarp();

        // prefetch next step's gather while MMAs run
        if (s + 1 < ns1) {
            #pragma unroll
            for (int u = 0; u < 4; ++u) {
                const int sl = 4 * (s + 1) + u;
                const int o0 = s_y0[sl], o1 = s_y1[sl];
                const float f0 = s_f0[sl], f1 = s_f1[sl];
                const float* pp = xb + (size_t)s_pl[sl] * HW + mbase + lane;
                #pragma unroll
                for (int c = 0; c < 4; ++c) {
                    float a0 = __ldg(pp + c * HW + o0);
                    float a1 = __ldg(pp + c * HW + o1);
                    vv[u * 4 + c] = a0 * f0 + a1 * f1;
                }
            }
        }

        const uint4* bfp = (const uint4*)s_bf + s * 64 + lane;
        #pragma unroll
        for (int np = 0; np < 2; ++np) {
            uint4 bv = bfp[np * 32];
            #pragma unroll
            for (int t = 0; t < 2; ++t) {
                mma16(acc[t][2*np],   ahi[t][0], ahi[t][1], ahi[t][2], ahi[t][3], bv.x, bv.y);
                mma16(acc[t][2*np+1], ahi[t][0], ahi[t][1], ahi[t][2], ahi[t][3], bv.z, bv.w);
            }
        }
    }

    // ---- epilogue 1: acc -> mid fp16x2 plane (+bias) ----
    #pragma unroll
    for (int t = 0; t < 2; ++t) {
        #pragma unroll
        for (int nt = 0; nt < 2; ++nt) {
            #pragma unroll
            for (int r = 0; r < 4; ++r) {
                int n   = nt * 8 + 2 * tig + (r & 1);
                int row = mbase + 16 * t + g + 8 * (r >> 1);
                float va = acc[t][nt][r]     + s_b1[n];
                float vb = acc[t][nt + 2][r] + s_b1[n + 16];
                s_mhi[n * 264 + 3 + row] = h2u(__floats2half2_rn(va, vb));
            }
        }
    }
    __syncthreads();

    // ---- B2 fragments: k = j*32 + kk, i = (kk>>1) + 16*(kk&1) ; uint4 ----
    for (int idx = tid; idx < 896; idx += 256) {
        int s  = idx >> 6;
        int np = (idx >> 5) & 1;
        int ln = idx & 31;
        int na = (2 * np) * 8 + (ln >> 2);
        int nb = na + 8;
        int tt = ln & 3;
        int j  = s >> 1;
        int ie = 8 * (s & 1) + tt;
        uint32_t u[4];
        #pragma unroll
        for (int e = 0; e < 4; ++e) {
            int n  = (e >> 1) ? nb : na;
            int i0 = ie + 4 * (e & 1);
            float va = 0.0f, vb = 0.0f;
            if (n < CCH) {
                int f = n >> 2, cq = n & 3;
                #pragma unroll
                for (int g7 = 0; g7 < 7; ++g7) {
                    float wm = w_m[f * 7 + g7];
                    int base = (g7 * 4 + cq) * CCH;
                    if (i0 < CCH)      va += wm * w_t[(base + i0) * KHH + j];
                    if (i0 + 16 < CCH) vb += wm * w_t[(base + i0 + 16) * KHH + j];
                }
            }
            u[e] = h2u(__floats2half2_rn(va, vb));
        }
        ((uint4*)s_bf)[idx] = make_uint4(u[0], u[1], u[2], u[3]);
    }
    #pragma unroll
    for (int t = 0; t < 2; ++t)
        #pragma unroll
        for (int nt = 0; nt < 4; ++nt)
            #pragma unroll
            for (int r = 0; r < 4; ++r) acc[t][nt][r] = 0.0f;
    __syncthreads();

    // =================== STAGE 2 : 14 k16 steps, single-A-term ================
    #pragma unroll 2
    for (int s = 0; s < 14; ++s) {
        const int j  = s >> 1;
        const int p0 = 8 * (s & 1) + tig;
        const int cb = mbase + g + j;
        uint32_t ahi[2][4];
        #pragma unroll
        for (int t = 0; t < 2; ++t) {
            int c0 = cb + 16 * t;
            ahi[t][0] = s_mhi[p0 * 264 + c0];
            ahi[t][1] = s_mhi[p0 * 264 + c0 + 8];
            ahi[t][2] = s_mhi[(p0 + 4) * 264 + c0];
            ahi[t][3] = s_mhi[(p0 + 4) * 264 + c0 + 8];
        }
        const uint4* bfp = (const uint4*)s_bf + s * 64 + lane;
        #pragma unroll
        for (int np = 0; np < 2; ++np) {
            uint4 bv = bfp[np * 32];
            #pragma unroll
            for (int t = 0; t < 2; ++t) {
                mma16(acc[t][2*np],   ahi[t][0], ahi[t][1], ahi[t][2], ahi[t][3], bv.x, bv.y);
                mma16(acc[t][2*np+1], ahi[t][0], ahi[t][1], ahi[t][2], ahi[t][3], bv.z, bv.w);
            }
        }
    }

    // ---- epilogue 2: acc -> out (+fused bias) ----
    float* ob = out + (size_t)b * CCH * HW + h * WWW;
    #pragma unroll
    for (int t = 0; t < 2; ++t) {
        int r0 = mbase + 16 * t + g;
        #pragma unroll
        for (int nt = 0; nt < 4; ++nt) {
            int n0 = nt * 8 + tig * 2;
            int n1 = n0 + 1;
            if (n0 < CCH) {
                float bq = s_B2[n0];
                ob[(size_t)n0 * HW + r0]     = acc[t][nt][0] + bq;
                ob[(size_t)n0 * HW + r0 + 8] = acc[t][nt][2] + bq;
            }
            if (n1 < CCH) {
                float bq = s_B2[n1];
                ob[(size_t)n1 * HW + r0]     = acc[t][nt][1] + bq;
                ob[(size_t)n1 * HW + r0 + 8] = acc[t][nt][3] + bq;
            }
        }
    }
}

// ---------------------------------------------------------------------------
extern "C" void kernel_launch(void* const* d_in, const int* in_sizes, int n_in,
                              void* d_out, int out_size) {
    const float* x      = (const float*)d_in[0];
    const float* weight = (const float*)d_in[1];
    const float* bias   = (const float*)d_in[2];
    const float* w_t    = (const float*)d_in[3];
    const float* b_t    = (const float*)d_in[4];
    const float* w_m    = (const float*)d_in[5];
    const float* b_m    = (const float*)d_in[6];
    float* out = (float*)d_out;

    cudaFuncSetAttribute(harmonic_mma_kernel,
                         cudaFuncAttributeMaxDynamicSharedMemorySize, SMEM_BYTES);
    harmonic_mma_kernel<<<BBATCH * HHH, 256, SMEM_BYTES>>>(
        x, weight, bias, w_t, b_t, w_m, b_m, out);
}

// round 12
// speedup vs baseline: 3.7086x; 1.1599x over previous
#include <cuda_runtime.h>
#include <cuda_fp16.h>
#include <cstdint>

#define BBATCH 8
#define CCH    28
#define HHH    256
#define WWW    256
#define KHH    7
#define NGI    49
#define HW     (HHH*WWW)
#define PADH   3

// smem u32-index layout
#define BF_OFF    0
#define BF_U32    3584
#define MIDH_OFF  (BF_OFF+BF_U32)      // 16 pair-rows x 264 = 4224
#define STG_OFF   (MIDH_OFF+4224)      // 8 warps x 320
#define TBL_OFF   (STG_OFF+2560)
#define SMEM_U32  (TBL_OFF + 56*6 + 64 + 16)
#define SMEM_BYTES (SMEM_U32*4)

// precomputed weight tables (setup kernel -> main kernel)
__device__ uint32_t d_b1p[NGI * 64];   // [gi][cp(2)][n(32)] packed half2
__device__ uint4    d_b2f[896];        // stage-2 B fragments

static __device__ __forceinline__ void mma16(float* d,
                                             uint32_t a0, uint32_t a1,
                                             uint32_t a2, uint32_t a3,
                                             uint32_t b0, uint32_t b1) {
    asm volatile(
        "mma.sync.aligned.m16n8k16.row.col.f32.f16.f16.f32 "
        "{%0,%1,%2,%3}, {%4,%5,%6,%7}, {%8,%9}, {%0,%1,%2,%3};"
        : "+f"(d[0]), "+f"(d[1]), "+f"(d[2]), "+f"(d[3])
        : "r"(a0), "r"(a1), "r"(a2), "r"(a3), "r"(b0), "r"(b1));
}
static __device__ __forceinline__ uint32_t h2u(__half2 h) {
    return *reinterpret_cast<uint32_t*>(&h);
}

// ---------------------------------------------------------------------------
// Setup: per-tap B1 half2 table + full B2 fragment array (h-independent).
// ---------------------------------------------------------------------------
__global__ void setup_bfrag_kernel(const float* __restrict__ weight,
                                   const float* __restrict__ w_t,
                                   const float* __restrict__ w_m) {
    int idx = blockIdx.x * blockDim.x + threadIdx.x;
    // B1 per-tap table: P[gi*64 + cp*32 + n] = half2(w[n][gc+2cp][ki], w[n][gc+2cp+1][ki])
    if (idx < NGI * 64) {
        int gi = idx >> 6;
        int cp = (idx >> 5) & 1;
        int n  = idx & 31;
        float va = 0.0f, vb = 0.0f;
        if (n < CCH) {
            int gc = (gi / KHH) * 4, ki = gi % KHH;
            va = weight[(n * CCH + gc + 2 * cp) * KHH + ki];
            vb = weight[(n * CCH + gc + 2 * cp + 1) * KHH + ki];
        }
        d_b1p[idx] = h2u(__floats2half2_rn(va, vb));
    }
    // B2 fragments: identical math to the previous in-kernel fill
    if (idx < 896) {
        int s  = idx >> 6;
        int np = (idx >> 5) & 1;
        int ln = idx & 31;
        int na = (2 * np) * 8 + (ln >> 2);
        int nb = na + 8;
        int tt = ln & 3;
        int j  = s >> 1;
        int ie = 8 * (s & 1) + tt;
        uint32_t u[4];
        #pragma unroll
        for (int e = 0; e < 4; ++e) {
            int n  = (e >> 1) ? nb : na;
            int i0 = ie + 4 * (e & 1);
            float va = 0.0f, vb = 0.0f;
            if (n < CCH) {
                int f = n >> 2, cq = n & 3;
                #pragma unroll
                for (int g7 = 0; g7 < 7; ++g7) {
                    float wm = w_m[f * 7 + g7];
                    int base = (g7 * 4 + cq) * CCH;
                    if (i0 < CCH)      va += wm * w_t[(base + i0) * KHH + j];
                    if (i0 + 16 < CCH) vb += wm * w_t[(base + i0 + 16) * KHH + j];
                }
            }
            u[e] = h2u(__floats2half2_rn(va, vb));
        }
        d_b2f[idx] = make_uint4(u[0], u[1], u[2], u[3]);
    }
}

// ---------------------------------------------------------------------------
__global__ void __launch_bounds__(256, 4)
harmonic_mma_kernel(const float* __restrict__ x,
                    const float* __restrict__ bias,
                    const float* __restrict__ b_t,
                    const float* __restrict__ w_m,
                    const float* __restrict__ b_m,
                    float* __restrict__ out) {
    extern __shared__ uint32_t smu[];
    uint32_t* s_bf  = smu + BF_OFF;
    uint32_t* s_mhi = smu + MIDH_OFF;
    uint32_t* s_stg = smu + STG_OFF;
    float*    s_f0  = (float*)(smu + TBL_OFF);
    float*    s_f1  = s_f0 + 56;
    int*      s_y0  = (int*)(s_f1 + 56);
    int*      s_y1  = s_y0 + 56;
    int*      s_pl  = s_y1 + 56;
    int*      s_gi  = s_pl + 56;
    float*    s_b1  = (float*)(s_gi + 56);
    float*    s_B2  = s_b1 + 32;
    int*      s_ns  = (int*)(s_B2 + 32);

    const int tid  = threadIdx.x;
    const int wid  = tid >> 5;
    const int lane = tid & 31;
    const int g    = lane >> 2;
    const int tig  = lane & 3;
    const int h    = blockIdx.x & 255;
    const int b    = blockIdx.x >> 8;
    const int mbase = wid * 32;

    // ---- phase A: raw per-h tables (scratch in BF region) ----
    float* r_f0 = (float*)s_bf;
    float* r_f1 = r_f0 + 49;
    int*   r_y0 = (int*)(r_f1 + 49);
    int*   r_y1 = r_y0 + 49;
    if (tid < NGI) {
        int gg = tid / KHH, ii = tid % KHH;
        float fh = (float)h, fg = (float)gg, fi = (float)ii;
        float t   = __fdiv_rn(fh + 1.0f, fg + 1.0f) * (fi + 1.0f);
        float off = -fi + t - (fh + 1.0f);
        float yp  = fh - (float)PADH + fi + off;
        float y0f = floorf(yp);
        float fy  = yp - y0f;
        int   y0i = (int)y0f;
        float v0 = (y0i >= 0 && y0i <= HHH - 1) ? 1.0f : 0.0f;
        float v1 = (y0i + 1 >= 0 && y0i + 1 <= HHH - 1) ? 1.0f : 0.0f;
        int y0c = y0i < 0 ? 0 : (y0i > HHH - 1 ? HHH - 1 : y0i);
        int y1i = y0i + 1;
        int y1c = y1i < 0 ? 0 : (y1i > HHH - 1 ? HHH - 1 : y1i);
        r_y0[tid] = y0c * WWW;
        r_y1[tid] = y1c * WWW;
        r_f0[tid] = (1.0f - fy) * v0;
        r_f1[tid] = fy * v1;
    }
    if (tid < 32) {
        s_b1[tid] = (tid < CCH) ? bias[tid] : 0.0f;
        float s = 0.0f;
        if (tid < CCH) {
            int f = tid >> 2, cq = tid & 3;
            s = b_m[f];
            #pragma unroll
            for (int g7 = 0; g7 < 7; ++g7) s += w_m[f * 7 + g7] * b_t[g7 * 4 + cq];
        }
        s_B2[tid] = s;
    }
    if (tid < 128) {
        int p = tid >> 3, c8 = tid & 7;
        int col = (c8 < 3) ? c8 : 256 + c8;
        s_mhi[p * 264 + col] = 0u;
    }
    __syncthreads();

    // ---- phase B: compact live taps ----
    if (tid == 0) {
        int nl = 0;
        for (int gi = 0; gi < NGI; ++gi) {
            float f0 = r_f0[gi], f1 = r_f1[gi];
            if (f0 != 0.0f || f1 != 0.0f) {
                s_f0[nl] = f0; s_f1[nl] = f1;
                s_y0[nl] = r_y0[gi]; s_y1[nl] = r_y1[gi];
                s_pl[nl] = (gi / KHH) * 4;
                s_gi[nl] = gi;
                ++nl;
            }
        }
        int ns1 = (nl + 3) >> 2;
        for (int p = nl; p < ns1 * 4; ++p) {
            s_f0[p] = 0.0f; s_f1[p] = 0.0f;
            s_y0[p] = 0;    s_y1[p] = 0;
            s_pl[p] = 0;    s_gi[p] = -1;
        }
        *s_ns = ns1;
    }
    __syncthreads();
    const int ns1 = *s_ns;

    // ---- B1 fragments from precomputed per-tap table ----
    for (int idx = tid; idx < ns1 * 64; idx += 256) {
        int s  = idx >> 6;
        int np = (idx >> 5) & 1;
        int ln = idx & 31;
        int na = 16 * np + (ln >> 2);
        int tt = ln & 3;
        int cpo = (tt & 1) * 32;
        int sb = 4 * s + (tt >> 1);
        int ga = s_gi[sb], gb = s_gi[sb + 2];
        uint32_t u0 = 0, u1 = 0, u2 = 0, u3 = 0;
        if (ga >= 0) {
            u0 = d_b1p[ga * 64 + cpo + na];
            u2 = d_b1p[ga * 64 + cpo + na + 8];
        }
        if (gb >= 0) {
            u1 = d_b1p[gb * 64 + cpo + na];
            u3 = d_b1p[gb * 64 + cpo + na + 8];
        }
        ((uint4*)s_bf)[idx] = make_uint4(u0, u1, u2, u3);
    }
    __syncthreads();

    const float* xb = x + (size_t)b * CCH * HW;
    uint32_t* stgh = s_stg + wid * 320;

    float acc[2][4][4];
    #pragma unroll
    for (int t = 0; t < 2; ++t)
        #pragma unroll
        for (int nt = 0; nt < 4; ++nt)
            #pragma unroll
            for (int r = 0; r < 4; ++r) acc[t][nt][r] = 0.0f;

    // =================== STAGE 1 : ns1 k16 steps, single-A-term ===============
    #pragma unroll 1
    for (int s = 0; s < ns1; ++s) {
        #pragma unroll
        for (int r = 0; r < 2; ++r) {
            float vv[8];
            #pragma unroll
            for (int tp = 0; tp < 2; ++tp) {
                const int sl = 4 * s + 2 * r + tp;
                const int o0 = s_y0[sl], o1 = s_y1[sl];
                const float f0 = s_f0[sl], f1 = s_f1[sl];
                const float* pp = xb + (size_t)s_pl[sl] * HW + mbase + lane;
                #pragma unroll
                for (int c = 0; c < 4; ++c) {
                    float a0 = __ldg(pp + c * HW + o0);
                    float a1 = __ldg(pp + c * HW + o1);
                    vv[tp * 4 + c] = a0 * f0 + a1 * f1;
                }
            }
            #pragma unroll
            for (int tp = 0; tp < 2; ++tp) {
                int kp = 4 * r + 2 * tp;
                stgh[kp * 40 + lane]       = h2u(__floats2half2_rn(vv[4*tp+0], vv[4*tp+1]));
                stgh[(kp + 1) * 40 + lane] = h2u(__floats2half2_rn(vv[4*tp+2], vv[4*tp+3]));
            }
        }
        __syncwarp();

        uint32_t ahi[2][4];
        #pragma unroll
        for (int t = 0; t < 2; ++t) {
            int mb2 = 16 * t + g;
            ahi[t][0] = stgh[tig * 40 + mb2];
            ahi[t][1] = stgh[tig * 40 + mb2 + 8];
            ahi[t][2] = stgh[(tig + 4) * 40 + mb2];
            ahi[t][3] = stgh[(tig + 4) * 40 + mb2 + 8];
        }
        __syncwarp();

        const uint4* bfp = (const uint4*)s_bf + s * 64 + lane;
        #pragma unroll
        for (int np = 0; np < 2; ++np) {
            uint4 bv = bfp[np * 32];
            #pragma unroll
            for (int t = 0; t < 2; ++t) {
                mma16(acc[t][2*np],   ahi[t][0], ahi[t][1], ahi[t][2], ahi[t][3], bv.x, bv.y);
                mma16(acc[t][2*np+1], ahi[t][0], ahi[t][1], ahi[t][2], ahi[t][3], bv.z, bv.w);
            }
        }
    }

    // ---- epilogue 1: acc -> mid fp16x2 plane (+bias) ----
    #pragma unroll
    for (int t = 0; t < 2; ++t) {
        #pragma unroll
        for (int nt = 0; nt < 2; ++nt) {
            #pragma unroll
            for (int r = 0; r < 4; ++r) {
                int n   = nt * 8 + 2 * tig + (r & 1);
                int row = mbase + 16 * t + g + 8 * (r >> 1);
                float va = acc[t][nt][r]     + s_b1[n];
                float vb = acc[t][nt + 2][r] + s_b1[n + 16];
                s_mhi[n * 264 + 3 + row] = h2u(__floats2half2_rn(va, vb));
            }
        }
    }
    __syncthreads();

    // ---- B2 fragments: straight copy from precomputed global ----
    for (int idx = tid; idx < 896; idx += 256)
        ((uint4*)s_bf)[idx] = d_b2f[idx];
    #pragma unroll
    for (int t = 0; t < 2; ++t)
        #pragma unroll
        for (int nt = 0; nt < 4; ++nt)
            #pragma unroll
            for (int r = 0; r < 4; ++r) acc[t][nt][r] = 0.0f;
    __syncthreads();

    // =================== STAGE 2 : 14 k16 steps, single-A-term ================
    #pragma unroll 2
    for (int s = 0; s < 14; ++s) {
        const int j  = s >> 1;
        const int p0 = 8 * (s & 1) + tig;
        const int cb = mbase + g + j;
        uint32_t ahi[2][4];
        #pragma unroll
        for (int t = 0; t < 2; ++t) {
            int c0 = cb + 16 * t;
            ahi[t][0] = s_mhi[p0 * 264 + c0];
            ahi[t][1] = s_mhi[p0 * 264 + c0 + 8];
            ahi[t][2] = s_mhi[(p0 + 4) * 264 + c0];
            ahi[t][3] = s_mhi[(p0 + 4) * 264 + c0 + 8];
        }
        const uint4* bfp = (const uint4*)s_bf + s * 64 + lane;
        #pragma unroll
        for (int np = 0; np < 2; ++np) {
            uint4 bv = bfp[np * 32];
            #pragma unroll
            for (int t = 0; t < 2; ++t) {
                mma16(acc[t][2*np],   ahi[t][0], ahi[t][1], ahi[t][2], ahi[t][3], bv.x, bv.y);
                mma16(acc[t][2*np+1], ahi[t][0], ahi[t][1], ahi[t][2], ahi[t][3], bv.z, bv.w);
            }
        }
    }

    // ---- epilogue 2: acc -> out (+fused bias) ----
    float* ob = out + (size_t)b * CCH * HW + h * WWW;
    #pragma unroll
    for (int t = 0; t < 2; ++t) {
        int r0 = mbase + 16 * t + g;
        #pragma unroll
        for (int nt = 0; nt < 4; ++nt) {
            int n0 = nt * 8 + tig * 2;
            int n1 = n0 + 1;
            if (n0 < CCH) {
                float bq = s_B2[n0];
                ob[(size_t)n0 * HW + r0]     = acc[t][nt][0] + bq;
                ob[(size_t)n0 * HW + r0 + 8] = acc[t][nt][2] + bq;
            }
            if (n1 < CCH) {
                float bq = s_B2[n1];
                ob[(size_t)n1 * HW + r0]     = acc[t][nt][1] + bq;
                ob[(size_t)n1 * HW + r0 + 8] = acc[t][nt][3] + bq;
            }
        }
    }
}

// ---------------------------------------------------------------------------
extern "C" void kernel_launch(void* const* d_in, const int* in_sizes, int n_in,
                              void* d_out, int out_size) {
    const float* x      = (const float*)d_in[0];
    const float* weight = (const float*)d_in[1];
    const float* bias   = (const float*)d_in[2];
    const float* w_t    = (const float*)d_in[3];
    const float* b_t    = (const float*)d_in[4];
    const float* w_m    = (const float*)d_in[5];
    const float* b_m    = (const float*)d_in[6];
    float* out = (float*)d_out;

    setup_bfrag_kernel<<<(NGI * 64 + 255) / 256, 256>>>(weight, w_t, w_m);

    cudaFuncSetAttribute(harmonic_mma_kernel,
                         cudaFuncAttributeMaxDynamicSharedMemorySize, SMEM_BYTES);
    harmonic_mma_kernel<<<BBATCH * HHH, 256, SMEM_BYTES>>>(
        x, bias, b_t, w_m, b_m, out);
}